// round 10
// baseline (speedup 1.0000x reference)
#include <cuda_runtime.h>
#include <cuda_fp16.h>
#include <cstdint>

// Problem constants
#define T_TOK 8192
#define DIM   1024
#define NEXP  16
#define INTER 2048
#define NA    16384
#define NAP   18432
#define NT_MAX 144

// ---------------- static device scratch --------------------------------------
__device__ int    g_poff[NEXP];
__device__ int    g_cursor[NEXP];
__device__ int    g_tile_e[NT_MAX];
__device__ int    g_tok_e[NA];
__device__ float  g_tok_w[NA];
__device__ int    g_tok_slot[NA];
__device__ __half g_Xg[(size_t)NAP * DIM];            // gathered tokens (fp16)
__device__ __half g_H [(size_t)NAP * INTER];          // GLU hidden (fp16)
__device__ float  g_O [(size_t)NAP * DIM];            // expert outputs (fp32)
__device__ __half g_W1h[(size_t)NEXP * INTER * DIM];  // W1^T [e][n][k] fp16
__device__ __half g_W3h[(size_t)NEXP * INTER * DIM];  // W3^T [e][n][k]
__device__ __half g_W2h[(size_t)NEXP * DIM * INTER];  // W2^T [e][n][k]

// ---------------- helpers ----------------------------------------------------
__device__ __forceinline__ float silu_f(float x) { return x / (1.0f + __expf(-x)); }

__device__ __forceinline__ void cp_async16(void* smem_dst, const void* gmem_src) {
    uint32_t s = (uint32_t)__cvta_generic_to_shared(smem_dst);
    asm volatile("cp.async.cg.shared.global [%0], [%1], 16;\n" :: "r"(s), "l"(gmem_src));
}
#define CP_COMMIT() asm volatile("cp.async.commit_group;\n" ::: "memory")
#define CP_WAIT1()  asm volatile("cp.async.wait_group 1;\n" ::: "memory")

__device__ __forceinline__ uint32_t smaddr(const void* p) {
    return (uint32_t)__cvta_generic_to_shared(p);
}

__device__ __forceinline__ void ldm_x4(uint32_t* r, uint32_t addr) {
    asm volatile("ldmatrix.sync.aligned.m8n8.x4.shared.b16 {%0,%1,%2,%3}, [%4];"
                 : "=r"(r[0]), "=r"(r[1]), "=r"(r[2]), "=r"(r[3]) : "r"(addr));
}

// m16n8k16 fp16 mma, fp32 accumulate
__device__ __forceinline__ void mma_f16(float* d, const uint32_t* a,
                                        uint32_t b0, uint32_t b1) {
    asm volatile(
        "mma.sync.aligned.m16n8k16.row.col.f32.f16.f16.f32 "
        "{%0,%1,%2,%3},{%4,%5,%6,%7},{%8,%9},{%0,%1,%2,%3};\n"
        : "+f"(d[0]), "+f"(d[1]), "+f"(d[2]), "+f"(d[3])
        : "r"(a[0]), "r"(a[1]), "r"(a[2]), "r"(a[3]), "r"(b0), "r"(b1));
}

// ---------------- fused prep: 3 weight transposes + gate ----------------------
// grid (64, 32, 49), block (32, 8).
//  z in [0,48): weight convert+transpose tile; z == 48: gate blocks.
__global__ void prep_kernel(const float* __restrict__ W1,
                            const float* __restrict__ W3,
                            const float* __restrict__ W2,
                            const float* __restrict__ x,
                            const float* __restrict__ Wg,
                            const float* __restrict__ bg) {
    __shared__ float t[32][33];
    int z = blockIdx.z;
    int tx = threadIdx.x, ty = threadIdx.y;
    int tid = ty * 32 + tx;

    if (z < 48) {
        // ---- transpose slice: [e][R][C] f32 -> [e][C][R] f16 ----
        int sel = z >> 4, e = z & 15;
        const float* src;
        __half* dst;
        int R, C, bx, by;
        if (sel == 0)      { src = W1; dst = g_W1h; R = DIM;   C = INTER; bx = blockIdx.x; by = blockIdx.y; }
        else if (sel == 1) { src = W3; dst = g_W3h; R = DIM;   C = INTER; bx = blockIdx.x; by = blockIdx.y; }
        else               { src = W2; dst = g_W2h; R = INTER; C = DIM;   bx = blockIdx.y; by = blockIdx.x; }
        size_t base = (size_t)e * R * C;
        src += base; dst += base;
        int xx = bx * 32 + tx;
        int y0 = by * 32;
#pragma unroll
        for (int j = 0; j < 4; j++)
            t[ty + 8 * j][tx] = src[(size_t)(y0 + ty + 8 * j) * C + xx];
        __syncthreads();
#pragma unroll
        for (int j = 0; j < 4; j++)
            dst[(size_t)(bx * 32 + ty + 8 * j) * R + (y0 + tx)] =
                __float2half_rn(t[tx][ty + 8 * j]);
        return;
    }

    // ---- gate slice: 4 tokens per warp, 32 tokens per block ----
    int fl = blockIdx.y * 64 + blockIdx.x;
    if (fl >= T_TOK / 32) return;
    int warp = tid >> 5, lane = tid & 31;
    int t0 = (fl * 8 + warp) * 4;
    const float* x0 = x + (size_t)t0 * DIM;

    float acc[4][NEXP];
#pragma unroll
    for (int tt = 0; tt < 4; tt++)
#pragma unroll
        for (int e = 0; e < NEXP; e++) acc[tt][e] = 0.0f;

    for (int d = lane; d < DIM; d += 32) {
        const float4* w4 = reinterpret_cast<const float4*>(Wg + (size_t)d * NEXP);
        float4 w0 = w4[0], w1 = w4[1], w2 = w4[2], w3 = w4[3];
        float xv[4];
#pragma unroll
        for (int tt = 0; tt < 4; tt++) xv[tt] = __ldg(x0 + (size_t)tt * DIM + d);
#pragma unroll
        for (int tt = 0; tt < 4; tt++) {
            float v = xv[tt];
            acc[tt][0]  += v * w0.x; acc[tt][1]  += v * w0.y;
            acc[tt][2]  += v * w0.z; acc[tt][3]  += v * w0.w;
            acc[tt][4]  += v * w1.x; acc[tt][5]  += v * w1.y;
            acc[tt][6]  += v * w1.z; acc[tt][7]  += v * w1.w;
            acc[tt][8]  += v * w2.x; acc[tt][9]  += v * w2.y;
            acc[tt][10] += v * w2.z; acc[tt][11] += v * w2.w;
            acc[tt][12] += v * w3.x; acc[tt][13] += v * w3.y;
            acc[tt][14] += v * w3.z; acc[tt][15] += v * w3.w;
        }
    }
#pragma unroll
    for (int tt = 0; tt < 4; tt++)
#pragma unroll
        for (int e = 0; e < NEXP; e++) {
            float v = acc[tt][e];
#pragma unroll
            for (int o = 16; o > 0; o >>= 1) v += __shfl_xor_sync(0xffffffffu, v, o);
            acc[tt][e] = v;
        }
    if (lane < 4) {
        int tk = t0 + lane;
        float fa[NEXP];
#pragma unroll
        for (int e = 0; e < NEXP; e++)
            fa[e] = (lane == 0) ? acc[0][e] : (lane == 1) ? acc[1][e]
                   : (lane == 2) ? acc[2][e] : acc[3][e];
        float l1 = -1e30f, l2 = -1e30f;
        int i1 = 0, i2 = 0;
#pragma unroll
        for (int e = 0; e < NEXP; e++) {
            float v = fa[e] + bg[e];
            if (v > l1) { l1 = v; i1 = e; }
        }
#pragma unroll
        for (int e = 0; e < NEXP; e++) {
            float v = fa[e] + bg[e];
            if (e != i1 && v > l2) { l2 = v; i2 = e; }
        }
        float e2 = __expf(l2 - l1);
        float w1v = 1.0f / (1.0f + e2);
        float w2v = e2 * w1v;
        g_tok_e[2 * tk]     = i1;
        g_tok_e[2 * tk + 1] = i2;
        g_tok_w[2 * tk]     = w1v;
        g_tok_w[2 * tk + 1] = w2v;
    }
}

// ---------------- offsets: histogram + padded prefix + tile map --------------
__global__ void offsets_kernel() {
    __shared__ int h[NEXP];
    int tid = threadIdx.x;
    if (tid < NEXP) h[tid] = 0;
    __syncthreads();
    for (int i = tid; i < NA; i += 256) atomicAdd(&h[g_tok_e[i]], 1);
    __syncthreads();
    if (tid == 0) {
        int run = 0, idx = 0;
        for (int e = 0; e < NEXP; e++) {
            g_poff[e]   = run;
            g_cursor[e] = 0;
            int pt = (h[e] + 127) >> 7;
            for (int i = 0; i < pt; i++) g_tile_e[idx++] = e;
            run += pt << 7;
        }
        for (; idx < NT_MAX; idx++) g_tile_e[idx] = -1;
    }
}

// ---------------- assign slots + gather (f32 -> fp16) ------------------------
__global__ void assign_gather_kernel(const float* __restrict__ x) {
    int aw   = (blockIdx.x * blockDim.x + threadIdx.x) >> 5;
    int lane = threadIdx.x & 31;
    if (aw >= NA) return;
    int t = aw >> 1;

    int slot = 0;
    if (lane == 0) {
        int e   = g_tok_e[aw];
        int pos = atomicAdd(&g_cursor[e], 1);
        slot    = g_poff[e] + pos;
        g_tok_slot[aw] = slot;
    }
    slot = __shfl_sync(0xffffffffu, slot, 0);

    const float2* src = reinterpret_cast<const float2*>(x + (size_t)t * DIM);
    __half2*      dst = reinterpret_cast<__half2*>(g_Xg + (size_t)slot * DIM);
#pragma unroll
    for (int i = 0; i < 16; i++) {
        int c = lane + 32 * i;
        dst[c] = __float22half2_rn(src[c]);
    }
}

// ---------------- GEMM tiles (fp16, ldmatrix) --------------------------------
#define BM  128
#define BN  128
#define BK  32
#define BKP 40               // half row pad: 80B stride, conflict-free, 16B-aligned
#define NSTAGE 3
#define TILE_ST (128 * BKP)  // 5120 halfs per 128-row tile stage
#define G1_SMEM (NSTAGE * 3 * TILE_ST * 2)   // A + B1 + B3 = 92160 B
#define G2_SMEM (NSTAGE * 2 * TILE_ST * 2)   // A + B      = 61440 B

// GEMM1 fused: H = silu(Xg@W1 + b1) * (Xg@W3 + b3)
__global__ __launch_bounds__(256, 1) void gemm1_kernel(
    const float* __restrict__ b1, const float* __restrict__ b3) {
    int e = g_tile_e[blockIdx.y];
    if (e < 0) return;
    int m0 = blockIdx.y * BM;
    int n0 = blockIdx.x * BN;

    const __half* A  = g_Xg  + (size_t)m0 * DIM;
    const __half* B1 = g_W1h + (size_t)e * INTER * DIM + (size_t)n0 * DIM;
    const __half* B3 = g_W3h + (size_t)e * INTER * DIM + (size_t)n0 * DIM;

    extern __shared__ __half sm[];
    __half* As  = sm;                        // [NSTAGE][128][BKP]
    __half* Bs1 = sm + NSTAGE * TILE_ST;     // [NSTAGE][128][BKP] (n-major)
    __half* Bs3 = Bs1 + NSTAGE * TILE_ST;

    int tid  = threadIdx.x;
    int lane = tid & 31, warp = tid >> 5;
    int wm = (warp >> 2) * 64, wn = (warp & 3) * 32;
    int g  = lane >> 2, tg = lane & 3;
    int rl = lane & 15, kh = (lane >> 4) * 8;

    float acc1[4][4][4] = {};
    float acc3[4][4][4] = {};

    const int KT = DIM / BK;   // 32

    auto load_stage = [&](int k0, int st) {
        __half* as  = As  + st * TILE_ST;
        __half* b1s = Bs1 + st * TILE_ST;
        __half* b3s = Bs3 + st * TILE_ST;
#pragma unroll
        for (int i = 0; i < 2; i++) {
            int idx = tid + i * 256;
            int r = idx >> 2, ch = idx & 3;
            cp_async16(as  + r * BKP + ch * 8, A  + (size_t)r * DIM + k0 + ch * 8);
            cp_async16(b1s + r * BKP + ch * 8, B1 + (size_t)r * DIM + k0 + ch * 8);
            cp_async16(b3s + r * BKP + ch * 8, B3 + (size_t)r * DIM + k0 + ch * 8);
        }
    };

    load_stage(0, 0);  CP_COMMIT();
    load_stage(BK, 1); CP_COMMIT();

    for (int kt = 0; kt < KT; kt++) {
        CP_WAIT1();
        __syncthreads();
        int nk = kt + 2;
        if (nk < KT) load_stage(nk * BK, nk % NSTAGE);
        CP_COMMIT();

        int st = kt % NSTAGE;
        const __half* as  = As  + st * TILE_ST;
        const __half* b1s = Bs1 + st * TILE_ST;
        const __half* b3s = Bs3 + st * TILE_ST;
#pragma unroll
        for (int ks = 0; ks < BK; ks += 16) {
            uint32_t af[4][4];
#pragma unroll
            for (int mi = 0; mi < 4; mi++)
                ldm_x4(af[mi], smaddr(as + (wm + mi * 16 + rl) * BKP + ks + kh));
            uint32_t bf1[2][4], bf3[2][4];
#pragma unroll
            for (int nj = 0; nj < 2; nj++) {
                ldm_x4(bf1[nj], smaddr(b1s + (wn + nj * 16 + rl) * BKP + ks + kh));
                ldm_x4(bf3[nj], smaddr(b3s + (wn + nj * 16 + rl) * BKP + ks + kh));
            }
#pragma unroll
            for (int mi = 0; mi < 4; mi++) {
#pragma unroll
                for (int ni = 0; ni < 4; ni++) {
                    int nj = ni >> 1, p = ni & 1;
                    mma_f16(acc1[mi][ni], af[mi], bf1[nj][p], bf1[nj][2 + p]);
                    mma_f16(acc3[mi][ni], af[mi], bf3[nj][p], bf3[nj][2 + p]);
                }
            }
        }
    }

    // epilogue: bias + silu-glu, write H (fp16)
#pragma unroll
    for (int mi = 0; mi < 4; mi++) {
#pragma unroll
        for (int ni = 0; ni < 4; ni++) {
            int r0 = m0 + wm + mi * 16 + g;
            int cg = n0 + wn + ni * 8 + tg * 2;
            float b1a = __ldg(b1 + e * INTER + cg), b1b = __ldg(b1 + e * INTER + cg + 1);
            float b3a = __ldg(b3 + e * INTER + cg), b3b = __ldg(b3 + e * INTER + cg + 1);
            float h0 = silu_f(acc1[mi][ni][0] + b1a) * (acc3[mi][ni][0] + b3a);
            float h1 = silu_f(acc1[mi][ni][1] + b1b) * (acc3[mi][ni][1] + b3b);
            float h2 = silu_f(acc1[mi][ni][2] + b1a) * (acc3[mi][ni][2] + b3a);
            float h3 = silu_f(acc1[mi][ni][3] + b1b) * (acc3[mi][ni][3] + b3b);
            *reinterpret_cast<__half2*>(&g_H[(size_t)r0 * INTER + cg]) =
                __floats2half2_rn(h0, h1);
            *reinterpret_cast<__half2*>(&g_H[(size_t)(r0 + 8) * INTER + cg]) =
                __floats2half2_rn(h2, h3);
        }
    }
}

// GEMM2: O = H @ W2 + b2
__global__ __launch_bounds__(256, 1) void gemm2_kernel(const float* __restrict__ b2) {
    int e = g_tile_e[blockIdx.y];
    if (e < 0) return;
    int m0 = blockIdx.y * BM;
    int n0 = blockIdx.x * BN;

    const __half* A = g_H   + (size_t)m0 * INTER;
    const __half* B = g_W2h + (size_t)e * DIM * INTER + (size_t)n0 * INTER;

    extern __shared__ __half sm[];
    __half* As = sm;                        // [NSTAGE][128][BKP]
    __half* Bs = sm + NSTAGE * TILE_ST;     // [NSTAGE][128][BKP]

    int tid  = threadIdx.x;
    int lane = tid & 31, warp = tid >> 5;
    int wm = (warp >> 2) * 64, wn = (warp & 3) * 32;
    int g  = lane >> 2, tg = lane & 3;
    int rl = lane & 15, kh = (lane >> 4) * 8;

    float acc[4][4][4] = {};

    const int KT = INTER / BK;   // 64

    auto load_stage = [&](int k0, int st) {
        __half* as = As + st * TILE_ST;
        __half* bs = Bs + st * TILE_ST;
#pragma unroll
        for (int i = 0; i < 2; i++) {
            int idx = tid + i * 256;
            int r = idx >> 2, ch = idx & 3;
            cp_async16(as + r * BKP + ch * 8, A + (size_t)r * INTER + k0 + ch * 8);
            cp_async16(bs + r * BKP + ch * 8, B + (size_t)r * INTER + k0 + ch * 8);
        }
    };

    load_stage(0, 0);  CP_COMMIT();
    load_stage(BK, 1); CP_COMMIT();

    for (int kt = 0; kt < KT; kt++) {
        CP_WAIT1();
        __syncthreads();
        int nk = kt + 2;
        if (nk < KT) load_stage(nk * BK, nk % NSTAGE);
        CP_COMMIT();

        int st = kt % NSTAGE;
        const __half* as = As + st * TILE_ST;
        const __half* bs = Bs + st * TILE_ST;
#pragma unroll
        for (int ks = 0; ks < BK; ks += 16) {
            uint32_t af[4][4];
#pragma unroll
            for (int mi = 0; mi < 4; mi++)
                ldm_x4(af[mi], smaddr(as + (wm + mi * 16 + rl) * BKP + ks + kh));
            uint32_t bf[2][4];
#pragma unroll
            for (int nj = 0; nj < 2; nj++)
                ldm_x4(bf[nj], smaddr(bs + (wn + nj * 16 + rl) * BKP + ks + kh));
#pragma unroll
            for (int mi = 0; mi < 4; mi++) {
#pragma unroll
                for (int ni = 0; ni < 4; ni++) {
                    int nj = ni >> 1, p = ni & 1;
                    mma_f16(acc[mi][ni], af[mi], bf[nj][p], bf[nj][2 + p]);
                }
            }
        }
    }

#pragma unroll
    for (int mi = 0; mi < 4; mi++) {
#pragma unroll
        for (int ni = 0; ni < 4; ni++) {
            int r0 = m0 + wm + mi * 16 + g;
            int cg = n0 + wn + ni * 8 + tg * 2;
            float ba = __ldg(b2 + e * DIM + cg), bb = __ldg(b2 + e * DIM + cg + 1);
            *reinterpret_cast<float2*>(&g_O[(size_t)r0 * DIM + cg]) =
                make_float2(acc[mi][ni][0] + ba, acc[mi][ni][1] + bb);
            *reinterpret_cast<float2*>(&g_O[(size_t)(r0 + 8) * DIM + cg]) =
                make_float2(acc[mi][ni][2] + ba, acc[mi][ni][3] + bb);
        }
    }
}

// ---------------- combine (warp per token) -----------------------------------
__global__ void combine_kernel(float* __restrict__ y) {
    int t    = (blockIdx.x * blockDim.x + threadIdx.x) >> 5;
    int lane = threadIdx.x & 31;
    if (t >= T_TOK) return;
    int   s0 = g_tok_slot[2 * t],  s1 = g_tok_slot[2 * t + 1];
    float w0 = g_tok_w[2 * t],     w1 = g_tok_w[2 * t + 1];
    const float4* o0 = reinterpret_cast<const float4*>(g_O + (size_t)s0 * DIM);
    const float4* o1 = reinterpret_cast<const float4*>(g_O + (size_t)s1 * DIM);
    float4* yr = reinterpret_cast<float4*>(y + (size_t)t * DIM);
#pragma unroll
    for (int i = 0; i < 8; i++) {
        int c = lane + 32 * i;
        float4 a = o0[c], b = o1[c], r;
        r.x = w0 * a.x + w1 * b.x;
        r.y = w0 * a.y + w1 * b.y;
        r.z = w0 * a.z + w1 * b.z;
        r.w = w0 * a.w + w1 * b.w;
        yr[c] = r;
    }
}

// ---------------- launcher ---------------------------------------------------
extern "C" void kernel_launch(void* const* d_in, const int* in_sizes, int n_in,
                              void* d_out, int out_size) {
    const float* x  = (const float*)d_in[0];
    const float* Wg = (const float*)d_in[1];
    const float* bg = (const float*)d_in[2];
    const float* W1 = (const float*)d_in[3];
    const float* b1 = (const float*)d_in[4];
    const float* W2 = (const float*)d_in[5];
    const float* b2 = (const float*)d_in[6];
    const float* W3 = (const float*)d_in[7];
    const float* b3 = (const float*)d_in[8];
    float* y = (float*)d_out;

    cudaFuncSetAttribute(gemm1_kernel, cudaFuncAttributeMaxDynamicSharedMemorySize, G1_SMEM);
    cudaFuncSetAttribute(gemm2_kernel, cudaFuncAttributeMaxDynamicSharedMemorySize, G2_SMEM);

    prep_kernel<<<dim3(64, 32, 49), dim3(32, 8)>>>(W1, W3, W2, x, Wg, bg);
    offsets_kernel<<<1, 256>>>();
    assign_gather_kernel<<<NA / 8, 256>>>(x);
    gemm1_kernel<<<dim3(INTER / BN, NT_MAX), 256, G1_SMEM>>>(b1, b3);
    gemm2_kernel<<<dim3(DIM / BN, NT_MAX), 256, G2_SMEM>>>(b2);
    combine_kernel<<<T_TOK / 8, 256>>>(y);
}

// round 11
// speedup vs baseline: 1.3547x; 1.3547x over previous
#include <cuda_runtime.h>
#include <cuda_fp16.h>
#include <cstdint>

// Problem constants
#define T_TOK 8192
#define DIM   1024
#define NEXP  16
#define INTER 2048
#define NA    16384
#define NAP   18432
#define NT_MAX 144

// ---------------- static device scratch --------------------------------------
__device__ int    g_counts[NEXP];
__device__ int    g_poff[NEXP];
__device__ int    g_cursor[NEXP];
__device__ int    g_tile_e[NT_MAX];
__device__ int    g_tok_e[NA];
__device__ float  g_tok_w[NA];
__device__ int    g_tok_slot[NA];
__device__ __half g_Xg[(size_t)NAP * DIM];            // gathered tokens (fp16)
__device__ __half g_H [(size_t)NAP * INTER];          // GLU hidden (fp16)
__device__ float  g_O [(size_t)NAP * DIM];            // expert outputs (fp32)
__device__ __half g_W1h[(size_t)NEXP * INTER * DIM];  // W1^T [e][n][k] fp16
__device__ __half g_W3h[(size_t)NEXP * INTER * DIM];  // W3^T [e][n][k]
__device__ __half g_W2h[(size_t)NEXP * DIM * INTER];  // W2^T [e][n][k]

// ---------------- helpers ----------------------------------------------------
__device__ __forceinline__ float silu_f(float x) { return x / (1.0f + __expf(-x)); }

__device__ __forceinline__ void cp_async16(void* smem_dst, const void* gmem_src) {
    uint32_t s = (uint32_t)__cvta_generic_to_shared(smem_dst);
    asm volatile("cp.async.cg.shared.global [%0], [%1], 16;\n" :: "r"(s), "l"(gmem_src));
}
#define CP_COMMIT() asm volatile("cp.async.commit_group;\n" ::: "memory")
#define CP_WAIT1()  asm volatile("cp.async.wait_group 1;\n" ::: "memory")

__device__ __forceinline__ uint32_t smaddr(const void* p) {
    return (uint32_t)__cvta_generic_to_shared(p);
}

__device__ __forceinline__ void ldm_x4(uint32_t* r, uint32_t addr) {
    asm volatile("ldmatrix.sync.aligned.m8n8.x4.shared.b16 {%0,%1,%2,%3}, [%4];"
                 : "=r"(r[0]), "=r"(r[1]), "=r"(r[2]), "=r"(r[3]) : "r"(addr));
}

// m16n8k16 fp16 mma, fp32 accumulate
__device__ __forceinline__ void mma_f16(float* d, const uint32_t* a,
                                        uint32_t b0, uint32_t b1) {
    asm volatile(
        "mma.sync.aligned.m16n8k16.row.col.f32.f16.f16.f32 "
        "{%0,%1,%2,%3},{%4,%5,%6,%7},{%8,%9},{%0,%1,%2,%3};\n"
        : "+f"(d[0]), "+f"(d[1]), "+f"(d[2]), "+f"(d[3])
        : "r"(a[0]), "r"(a[1]), "r"(a[2]), "r"(a[3]), "r"(b0), "r"(b1));
}

// ---------------- weight convert + transpose ([e][R][C]f32 -> [e][C][R]f16) --
__global__ void convt_kernel(const float* __restrict__ src, int sel, int R, int C) {
    __half* dst = (sel == 0) ? g_W1h : ((sel == 1) ? g_W3h : g_W2h);
    if (sel == 0 && blockIdx.x == 0 && blockIdx.y == 0 && blockIdx.z == 0 &&
        threadIdx.y == 0 && threadIdx.x < NEXP)
        g_counts[threadIdx.x] = 0;
    __shared__ float t[32][33];
    size_t base = (size_t)blockIdx.z * R * C;
    src += base; dst += base;
    int tx = threadIdx.x, ty = threadIdx.y;
    int x  = blockIdx.x * 32 + tx;
    int y0 = blockIdx.y * 32;
#pragma unroll
    for (int j = 0; j < 4; j++)
        t[ty + 8 * j][tx] = src[(size_t)(y0 + ty + 8 * j) * C + x];
    __syncthreads();
#pragma unroll
    for (int j = 0; j < 4; j++)
        dst[(size_t)(blockIdx.x * 32 + ty + 8 * j) * R + (y0 + tx)] =
            __float2half_rn(t[tx][ty + 8 * j]);
}

// ---------------- gate: 4 tokens per warp ------------------------------------
__global__ void gate_kernel(const float* __restrict__ x,
                            const float* __restrict__ Wg,
                            const float* __restrict__ bg) {
    int gw   = (blockIdx.x * blockDim.x + threadIdx.x) >> 5;
    int lane = threadIdx.x & 31;
    int t0   = gw * 4;
    if (t0 >= T_TOK) return;
    const float* x0 = x + (size_t)t0 * DIM;

    float acc[4][NEXP];
#pragma unroll
    for (int t = 0; t < 4; t++)
#pragma unroll
        for (int e = 0; e < NEXP; e++) acc[t][e] = 0.0f;

    for (int d = lane; d < DIM; d += 32) {
        const float4* w4 = reinterpret_cast<const float4*>(Wg + (size_t)d * NEXP);
        float4 w0 = w4[0], w1 = w4[1], w2 = w4[2], w3 = w4[3];
        float xv[4];
#pragma unroll
        for (int t = 0; t < 4; t++) xv[t] = __ldg(x0 + (size_t)t * DIM + d);
#pragma unroll
        for (int t = 0; t < 4; t++) {
            float v = xv[t];
            acc[t][0]  += v * w0.x; acc[t][1]  += v * w0.y;
            acc[t][2]  += v * w0.z; acc[t][3]  += v * w0.w;
            acc[t][4]  += v * w1.x; acc[t][5]  += v * w1.y;
            acc[t][6]  += v * w1.z; acc[t][7]  += v * w1.w;
            acc[t][8]  += v * w2.x; acc[t][9]  += v * w2.y;
            acc[t][10] += v * w2.z; acc[t][11] += v * w2.w;
            acc[t][12] += v * w3.x; acc[t][13] += v * w3.y;
            acc[t][14] += v * w3.z; acc[t][15] += v * w3.w;
        }
    }
#pragma unroll
    for (int t = 0; t < 4; t++)
#pragma unroll
        for (int e = 0; e < NEXP; e++) {
            float v = acc[t][e];
#pragma unroll
            for (int o = 16; o > 0; o >>= 1) v += __shfl_xor_sync(0xffffffffu, v, o);
            acc[t][e] = v;
        }
    if (lane < 4) {
        int t = t0 + lane;
        float fa[NEXP];
#pragma unroll
        for (int e = 0; e < NEXP; e++)
            fa[e] = (lane == 0) ? acc[0][e] : (lane == 1) ? acc[1][e]
                   : (lane == 2) ? acc[2][e] : acc[3][e];
        float l1 = -1e30f, l2 = -1e30f;
        int i1 = 0, i2 = 0;
#pragma unroll
        for (int e = 0; e < NEXP; e++) {
            float v = fa[e] + bg[e];
            if (v > l1) { l1 = v; i1 = e; }
        }
#pragma unroll
        for (int e = 0; e < NEXP; e++) {
            float v = fa[e] + bg[e];
            if (e != i1 && v > l2) { l2 = v; i2 = e; }
        }
        float e2 = __expf(l2 - l1);
        float w1v = 1.0f / (1.0f + e2);
        float w2v = e2 * w1v;
        g_tok_e[2 * t]     = i1;
        g_tok_e[2 * t + 1] = i2;
        g_tok_w[2 * t]     = w1v;
        g_tok_w[2 * t + 1] = w2v;
        atomicAdd(&g_counts[i1], 1);
        atomicAdd(&g_counts[i2], 1);
    }
}

// ---------------- offsets: padded prefix + tile map --------------------------
__global__ void offsets_kernel() {
    if (threadIdx.x != 0 || blockIdx.x != 0) return;
    int run = 0, idx = 0;
    for (int e = 0; e < NEXP; e++) {
        g_poff[e]   = run;
        g_cursor[e] = 0;
        int c  = g_counts[e];
        int pt = (c + 127) >> 7;
        for (int i = 0; i < pt; i++) g_tile_e[idx++] = e;
        run += pt << 7;
    }
    for (; idx < NT_MAX; idx++) g_tile_e[idx] = -1;
}

// ---------------- assign slots + gather (f32 -> fp16) ------------------------
__global__ void assign_gather_kernel(const float* __restrict__ x) {
    int aw   = (blockIdx.x * blockDim.x + threadIdx.x) >> 5;
    int lane = threadIdx.x & 31;
    if (aw >= NA) return;
    int t = aw >> 1;

    int slot = 0;
    if (lane == 0) {
        int e   = g_tok_e[aw];
        int pos = atomicAdd(&g_cursor[e], 1);
        slot    = g_poff[e] + pos;
        g_tok_slot[aw] = slot;
    }
    slot = __shfl_sync(0xffffffffu, slot, 0);

    const float2* src = reinterpret_cast<const float2*>(x + (size_t)t * DIM);
    __half2*      dst = reinterpret_cast<__half2*>(g_Xg + (size_t)slot * DIM);
#pragma unroll
    for (int i = 0; i < 16; i++) {
        int c = lane + 32 * i;
        dst[c] = __float22half2_rn(src[c]);
    }
}

// ---------------- GEMM tiles (fp16, ldmatrix, 512 threads) -------------------
#define BM  128
#define BN  128
#define BK  32
#define BKP 40               // half row pad: 80B stride, conflict-free, 16B-aligned
#define NSTAGE 3
#define TILE_ST (128 * BKP)  // 5120 halfs per 128-row tile stage
#define G1_SMEM (NSTAGE * 3 * TILE_ST * 2)   // A + B1 + B3 = 92160 B
#define G2_SMEM (NSTAGE * 2 * TILE_ST * 2)   // A + B      = 61440 B

// GEMM1 fused: H = silu(Xg@W1 + b1) * (Xg@W3 + b3). 16 warps, warp tile 32x32.
__global__ __launch_bounds__(512, 1) void gemm1_kernel(
    const float* __restrict__ b1, const float* __restrict__ b3) {
    int e = g_tile_e[blockIdx.y];
    if (e < 0) return;
    int m0 = blockIdx.y * BM;
    int n0 = blockIdx.x * BN;

    const __half* A  = g_Xg  + (size_t)m0 * DIM;
    const __half* B1 = g_W1h + (size_t)e * INTER * DIM + (size_t)n0 * DIM;
    const __half* B3 = g_W3h + (size_t)e * INTER * DIM + (size_t)n0 * DIM;

    extern __shared__ __half sm[];
    __half* As  = sm;                        // [NSTAGE][128][BKP]
    __half* Bs1 = sm + NSTAGE * TILE_ST;     // [NSTAGE][128][BKP] (n-major)
    __half* Bs3 = Bs1 + NSTAGE * TILE_ST;

    int tid  = threadIdx.x;
    int lane = tid & 31, warp = tid >> 5;            // 0..15
    int wm = (warp >> 2) * 32, wn = (warp & 3) * 32; // 4x4 warp grid
    int g  = lane >> 2, tg = lane & 3;
    int rl = lane & 15, kh = (lane >> 4) * 8;

    float acc1[2][4][4] = {};
    float acc3[2][4][4] = {};

    const int KT = DIM / BK;   // 32

    auto load_stage = [&](int k0, int st) {
        __half* as  = As  + st * TILE_ST;
        __half* b1s = Bs1 + st * TILE_ST;
        __half* b3s = Bs3 + st * TILE_ST;
        int r = tid >> 2, ch = tid & 3;              // 512 threads = 128x4 chunks
        cp_async16(as  + r * BKP + ch * 8, A  + (size_t)r * DIM + k0 + ch * 8);
        cp_async16(b1s + r * BKP + ch * 8, B1 + (size_t)r * DIM + k0 + ch * 8);
        cp_async16(b3s + r * BKP + ch * 8, B3 + (size_t)r * DIM + k0 + ch * 8);
    };

    load_stage(0, 0);  CP_COMMIT();
    load_stage(BK, 1); CP_COMMIT();

    for (int kt = 0; kt < KT; kt++) {
        CP_WAIT1();
        __syncthreads();
        int nk = kt + 2;
        if (nk < KT) load_stage(nk * BK, nk % NSTAGE);
        CP_COMMIT();

        int st = kt % NSTAGE;
        const __half* as  = As  + st * TILE_ST;
        const __half* b1s = Bs1 + st * TILE_ST;
        const __half* b3s = Bs3 + st * TILE_ST;
#pragma unroll
        for (int ks = 0; ks < BK; ks += 16) {
            uint32_t af[2][4];
#pragma unroll
            for (int mi = 0; mi < 2; mi++)
                ldm_x4(af[mi], smaddr(as + (wm + mi * 16 + rl) * BKP + ks + kh));
            uint32_t bf1[2][4], bf3[2][4];
#pragma unroll
            for (int nj = 0; nj < 2; nj++) {
                ldm_x4(bf1[nj], smaddr(b1s + (wn + nj * 16 + rl) * BKP + ks + kh));
                ldm_x4(bf3[nj], smaddr(b3s + (wn + nj * 16 + rl) * BKP + ks + kh));
            }
#pragma unroll
            for (int mi = 0; mi < 2; mi++) {
#pragma unroll
                for (int ni = 0; ni < 4; ni++) {
                    int nj = ni >> 1, p = ni & 1;
                    mma_f16(acc1[mi][ni], af[mi], bf1[nj][p], bf1[nj][2 + p]);
                    mma_f16(acc3[mi][ni], af[mi], bf3[nj][p], bf3[nj][2 + p]);
                }
            }
        }
    }

    // epilogue: bias + silu-glu, write H (fp16)
#pragma unroll
    for (int mi = 0; mi < 2; mi++) {
#pragma unroll
        for (int ni = 0; ni < 4; ni++) {
            int r0 = m0 + wm + mi * 16 + g;
            int cg = n0 + wn + ni * 8 + tg * 2;
            float b1a = __ldg(b1 + e * INTER + cg), b1b = __ldg(b1 + e * INTER + cg + 1);
            float b3a = __ldg(b3 + e * INTER + cg), b3b = __ldg(b3 + e * INTER + cg + 1);
            float h0 = silu_f(acc1[mi][ni][0] + b1a) * (acc3[mi][ni][0] + b3a);
            float h1 = silu_f(acc1[mi][ni][1] + b1b) * (acc3[mi][ni][1] + b3b);
            float h2 = silu_f(acc1[mi][ni][2] + b1a) * (acc3[mi][ni][2] + b3a);
            float h3 = silu_f(acc1[mi][ni][3] + b1b) * (acc3[mi][ni][3] + b3b);
            *reinterpret_cast<__half2*>(&g_H[(size_t)r0 * INTER + cg]) =
                __floats2half2_rn(h0, h1);
            *reinterpret_cast<__half2*>(&g_H[(size_t)(r0 + 8) * INTER + cg]) =
                __floats2half2_rn(h2, h3);
        }
    }
}

// GEMM2: O = H @ W2 + b2. 16 warps, warp tile 32x32.
__global__ __launch_bounds__(512, 1) void gemm2_kernel(const float* __restrict__ b2) {
    int e = g_tile_e[blockIdx.y];
    if (e < 0) return;
    int m0 = blockIdx.y * BM;
    int n0 = blockIdx.x * BN;

    const __half* A = g_H   + (size_t)m0 * INTER;
    const __half* B = g_W2h + (size_t)e * DIM * INTER + (size_t)n0 * INTER;

    extern __shared__ __half sm[];
    __half* As = sm;                        // [NSTAGE][128][BKP]
    __half* Bs = sm + NSTAGE * TILE_ST;     // [NSTAGE][128][BKP]

    int tid  = threadIdx.x;
    int lane = tid & 31, warp = tid >> 5;
    int wm = (warp >> 2) * 32, wn = (warp & 3) * 32;
    int g  = lane >> 2, tg = lane & 3;
    int rl = lane & 15, kh = (lane >> 4) * 8;

    float acc[2][4][4] = {};

    const int KT = INTER / BK;   // 64

    auto load_stage = [&](int k0, int st) {
        __half* as = As + st * TILE_ST;
        __half* bs = Bs + st * TILE_ST;
        int r = tid >> 2, ch = tid & 3;
        cp_async16(as + r * BKP + ch * 8, A + (size_t)r * INTER + k0 + ch * 8);
        cp_async16(bs + r * BKP + ch * 8, B + (size_t)r * INTER + k0 + ch * 8);
    };

    load_stage(0, 0);  CP_COMMIT();
    load_stage(BK, 1); CP_COMMIT();

    for (int kt = 0; kt < KT; kt++) {
        CP_WAIT1();
        __syncthreads();
        int nk = kt + 2;
        if (nk < KT) load_stage(nk * BK, nk % NSTAGE);
        CP_COMMIT();

        int st = kt % NSTAGE;
        const __half* as = As + st * TILE_ST;
        const __half* bs = Bs + st * TILE_ST;
#pragma unroll
        for (int ks = 0; ks < BK; ks += 16) {
            uint32_t af[2][4];
#pragma unroll
            for (int mi = 0; mi < 2; mi++)
                ldm_x4(af[mi], smaddr(as + (wm + mi * 16 + rl) * BKP + ks + kh));
            uint32_t bf[2][4];
#pragma unroll
            for (int nj = 0; nj < 2; nj++)
                ldm_x4(bf[nj], smaddr(bs + (wn + nj * 16 + rl) * BKP + ks + kh));
#pragma unroll
            for (int mi = 0; mi < 2; mi++) {
#pragma unroll
                for (int ni = 0; ni < 4; ni++) {
                    int nj = ni >> 1, p = ni & 1;
                    mma_f16(acc[mi][ni], af[mi], bf[nj][p], bf[nj][2 + p]);
                }
            }
        }
    }

#pragma unroll
    for (int mi = 0; mi < 2; mi++) {
#pragma unroll
        for (int ni = 0; ni < 4; ni++) {
            int r0 = m0 + wm + mi * 16 + g;
            int cg = n0 + wn + ni * 8 + tg * 2;
            float ba = __ldg(b2 + e * DIM + cg), bb = __ldg(b2 + e * DIM + cg + 1);
            *reinterpret_cast<float2*>(&g_O[(size_t)r0 * DIM + cg]) =
                make_float2(acc[mi][ni][0] + ba, acc[mi][ni][1] + bb);
            *reinterpret_cast<float2*>(&g_O[(size_t)(r0 + 8) * DIM + cg]) =
                make_float2(acc[mi][ni][2] + ba, acc[mi][ni][3] + bb);
        }
    }
}

// ---------------- combine (warp per token) -----------------------------------
__global__ void combine_kernel(float* __restrict__ y) {
    int t    = (blockIdx.x * blockDim.x + threadIdx.x) >> 5;
    int lane = threadIdx.x & 31;
    if (t >= T_TOK) return;
    int   s0 = g_tok_slot[2 * t],  s1 = g_tok_slot[2 * t + 1];
    float w0 = g_tok_w[2 * t],     w1 = g_tok_w[2 * t + 1];
    const float4* o0 = reinterpret_cast<const float4*>(g_O + (size_t)s0 * DIM);
    const float4* o1 = reinterpret_cast<const float4*>(g_O + (size_t)s1 * DIM);
    float4* yr = reinterpret_cast<float4*>(y + (size_t)t * DIM);
#pragma unroll
    for (int i = 0; i < 8; i++) {
        int c = lane + 32 * i;
        float4 a = o0[c], b = o1[c], r;
        r.x = w0 * a.x + w1 * b.x;
        r.y = w0 * a.y + w1 * b.y;
        r.z = w0 * a.z + w1 * b.z;
        r.w = w0 * a.w + w1 * b.w;
        yr[c] = r;
    }
}

// ---------------- launcher ---------------------------------------------------
extern "C" void kernel_launch(void* const* d_in, const int* in_sizes, int n_in,
                              void* d_out, int out_size) {
    const float* x  = (const float*)d_in[0];
    const float* Wg = (const float*)d_in[1];
    const float* bg = (const float*)d_in[2];
    const float* W1 = (const float*)d_in[3];
    const float* b1 = (const float*)d_in[4];
    const float* W2 = (const float*)d_in[5];
    const float* b2 = (const float*)d_in[6];
    const float* W3 = (const float*)d_in[7];
    const float* b3 = (const float*)d_in[8];
    float* y = (float*)d_out;

    cudaFuncSetAttribute(gemm1_kernel, cudaFuncAttributeMaxDynamicSharedMemorySize, G1_SMEM);
    cudaFuncSetAttribute(gemm2_kernel, cudaFuncAttributeMaxDynamicSharedMemorySize, G2_SMEM);

    // fp16 weight transposes: [e][n][k] (sel 0 also resets g_counts)
    convt_kernel<<<dim3(INTER / 32, DIM / 32, NEXP), dim3(32, 8)>>>(W1, 0, DIM, INTER);
    convt_kernel<<<dim3(INTER / 32, DIM / 32, NEXP), dim3(32, 8)>>>(W3, 1, DIM, INTER);
    convt_kernel<<<dim3(DIM / 32, INTER / 32, NEXP), dim3(32, 8)>>>(W2, 2, INTER, DIM);

    gate_kernel<<<T_TOK / 32, 256>>>(x, Wg, bg);
    offsets_kernel<<<1, 1>>>();
    assign_gather_kernel<<<NA / 8, 256>>>(x);
    gemm1_kernel<<<dim3(INTER / BN, NT_MAX), 512, G1_SMEM>>>(b1, b3);
    gemm2_kernel<<<dim3(DIM / BN, NT_MAX), 512, G2_SMEM>>>(b2);
    combine_kernel<<<T_TOK / 8, 256>>>(y);
}

// round 12
// speedup vs baseline: 1.3788x; 1.0178x over previous
#include <cuda_runtime.h>
#include <cuda_fp16.h>
#include <cstdint>

// Problem constants
#define T_TOK 8192
#define DIM   1024
#define NEXP  16
#define INTER 2048
#define NA    16384
#define NAP   18432
#define NT_MAX 144

// ---------------- static device scratch --------------------------------------
__device__ int    g_counts[NEXP];
__device__ int    g_poff[NEXP];
__device__ int    g_cursor[NEXP];
__device__ int    g_tile_e[NT_MAX];
__device__ int    g_tok_e[NA];
__device__ float  g_tok_w[NA];
__device__ int    g_tok_slot[NA];
__device__ __half g_Xg[(size_t)NAP * DIM];            // gathered tokens (fp16)
__device__ __half g_H [(size_t)NAP * INTER];          // GLU hidden (fp16)
__device__ float  g_O [(size_t)NAP * DIM];            // expert outputs (fp32)
__device__ __half g_W1h[(size_t)NEXP * INTER * DIM];  // W1^T [e][n][k] fp16
__device__ __half g_W3h[(size_t)NEXP * INTER * DIM];  // W3^T [e][n][k]
__device__ __half g_W2h[(size_t)NEXP * DIM * INTER];  // W2^T [e][n][k]

// ---------------- helpers ----------------------------------------------------
__device__ __forceinline__ float silu_f(float x) { return x / (1.0f + __expf(-x)); }

__device__ __forceinline__ void cp_async16(void* smem_dst, const void* gmem_src) {
    uint32_t s = (uint32_t)__cvta_generic_to_shared(smem_dst);
    asm volatile("cp.async.cg.shared.global [%0], [%1], 16;\n" :: "r"(s), "l"(gmem_src));
}
#define CP_COMMIT() asm volatile("cp.async.commit_group;\n" ::: "memory")
#define CP_WAIT1()  asm volatile("cp.async.wait_group 1;\n" ::: "memory")

__device__ __forceinline__ uint32_t smaddr(const void* p) {
    return (uint32_t)__cvta_generic_to_shared(p);
}

__device__ __forceinline__ void ldm_x4(uint32_t* r, uint32_t addr) {
    asm volatile("ldmatrix.sync.aligned.m8n8.x4.shared.b16 {%0,%1,%2,%3}, [%4];"
                 : "=r"(r[0]), "=r"(r[1]), "=r"(r[2]), "=r"(r[3]) : "r"(addr));
}

// m16n8k16 fp16 mma, fp32 accumulate
__device__ __forceinline__ void mma_f16(float* d, const uint32_t* a,
                                        uint32_t b0, uint32_t b1) {
    asm volatile(
        "mma.sync.aligned.m16n8k16.row.col.f32.f16.f16.f32 "
        "{%0,%1,%2,%3},{%4,%5,%6,%7},{%8,%9},{%0,%1,%2,%3};\n"
        : "+f"(d[0]), "+f"(d[1]), "+f"(d[2]), "+f"(d[3])
        : "r"(a[0]), "r"(a[1]), "r"(a[2]), "r"(a[3]), "r"(b0), "r"(b1));
}

// ---------------- weight convert + transpose ([e][R][C]f32 -> [e][C][R]f16) --
__global__ void convt_kernel(const float* __restrict__ src, int sel, int R, int C) {
    __half* dst = (sel == 0) ? g_W1h : ((sel == 1) ? g_W3h : g_W2h);
    if (sel == 0 && blockIdx.x == 0 && blockIdx.y == 0 && blockIdx.z == 0 &&
        threadIdx.y == 0 && threadIdx.x < NEXP)
        g_counts[threadIdx.x] = 0;
    __shared__ float t[32][33];
    size_t base = (size_t)blockIdx.z * R * C;
    src += base; dst += base;
    int tx = threadIdx.x, ty = threadIdx.y;
    int x  = blockIdx.x * 32 + tx;
    int y0 = blockIdx.y * 32;
#pragma unroll
    for (int j = 0; j < 4; j++)
        t[ty + 8 * j][tx] = src[(size_t)(y0 + ty + 8 * j) * C + x];
    __syncthreads();
#pragma unroll
    for (int j = 0; j < 4; j++)
        dst[(size_t)(blockIdx.x * 32 + ty + 8 * j) * R + (y0 + tx)] =
            __float2half_rn(t[tx][ty + 8 * j]);
}

// ---------------- gate: 4 tokens per warp ------------------------------------
__global__ void gate_kernel(const float* __restrict__ x,
                            const float* __restrict__ Wg,
                            const float* __restrict__ bg) {
    int gw   = (blockIdx.x * blockDim.x + threadIdx.x) >> 5;
    int lane = threadIdx.x & 31;
    int t0   = gw * 4;
    if (t0 >= T_TOK) return;
    const float* x0 = x + (size_t)t0 * DIM;

    float acc[4][NEXP];
#pragma unroll
    for (int t = 0; t < 4; t++)
#pragma unroll
        for (int e = 0; e < NEXP; e++) acc[t][e] = 0.0f;

    for (int d = lane; d < DIM; d += 32) {
        const float4* w4 = reinterpret_cast<const float4*>(Wg + (size_t)d * NEXP);
        float4 w0 = w4[0], w1 = w4[1], w2 = w4[2], w3 = w4[3];
        float xv[4];
#pragma unroll
        for (int t = 0; t < 4; t++) xv[t] = __ldg(x0 + (size_t)t * DIM + d);
#pragma unroll
        for (int t = 0; t < 4; t++) {
            float v = xv[t];
            acc[t][0]  += v * w0.x; acc[t][1]  += v * w0.y;
            acc[t][2]  += v * w0.z; acc[t][3]  += v * w0.w;
            acc[t][4]  += v * w1.x; acc[t][5]  += v * w1.y;
            acc[t][6]  += v * w1.z; acc[t][7]  += v * w1.w;
            acc[t][8]  += v * w2.x; acc[t][9]  += v * w2.y;
            acc[t][10] += v * w2.z; acc[t][11] += v * w2.w;
            acc[t][12] += v * w3.x; acc[t][13] += v * w3.y;
            acc[t][14] += v * w3.z; acc[t][15] += v * w3.w;
        }
    }
#pragma unroll
    for (int t = 0; t < 4; t++)
#pragma unroll
        for (int e = 0; e < NEXP; e++) {
            float v = acc[t][e];
#pragma unroll
            for (int o = 16; o > 0; o >>= 1) v += __shfl_xor_sync(0xffffffffu, v, o);
            acc[t][e] = v;
        }
    if (lane < 4) {
        int t = t0 + lane;
        float fa[NEXP];
#pragma unroll
        for (int e = 0; e < NEXP; e++)
            fa[e] = (lane == 0) ? acc[0][e] : (lane == 1) ? acc[1][e]
                   : (lane == 2) ? acc[2][e] : acc[3][e];
        float l1 = -1e30f, l2 = -1e30f;
        int i1 = 0, i2 = 0;
#pragma unroll
        for (int e = 0; e < NEXP; e++) {
            float v = fa[e] + bg[e];
            if (v > l1) { l1 = v; i1 = e; }
        }
#pragma unroll
        for (int e = 0; e < NEXP; e++) {
            float v = fa[e] + bg[e];
            if (e != i1 && v > l2) { l2 = v; i2 = e; }
        }
        float e2 = __expf(l2 - l1);
        float w1v = 1.0f / (1.0f + e2);
        float w2v = e2 * w1v;
        g_tok_e[2 * t]     = i1;
        g_tok_e[2 * t + 1] = i2;
        g_tok_w[2 * t]     = w1v;
        g_tok_w[2 * t + 1] = w2v;
        atomicAdd(&g_counts[i1], 1);
        atomicAdd(&g_counts[i2], 1);
    }
}

// ---------------- offsets: padded prefix + tile map --------------------------
__global__ void offsets_kernel() {
    if (threadIdx.x != 0 || blockIdx.x != 0) return;
    int run = 0, idx = 0;
    for (int e = 0; e < NEXP; e++) {
        g_poff[e]   = run;
        g_cursor[e] = 0;
        int c  = g_counts[e];
        int pt = (c + 127) >> 7;
        for (int i = 0; i < pt; i++) g_tile_e[idx++] = e;
        run += pt << 7;
    }
    for (; idx < NT_MAX; idx++) g_tile_e[idx] = -1;
}

// ---------------- assign slots + gather (f32 -> fp16) ------------------------
__global__ void assign_gather_kernel(const float* __restrict__ x) {
    int aw   = (blockIdx.x * blockDim.x + threadIdx.x) >> 5;
    int lane = threadIdx.x & 31;
    if (aw >= NA) return;
    int t = aw >> 1;

    int slot = 0;
    if (lane == 0) {
        int e   = g_tok_e[aw];
        int pos = atomicAdd(&g_cursor[e], 1);
        slot    = g_poff[e] + pos;
        g_tok_slot[aw] = slot;
    }
    slot = __shfl_sync(0xffffffffu, slot, 0);

    const float2* src = reinterpret_cast<const float2*>(x + (size_t)t * DIM);
    __half2*      dst = reinterpret_cast<__half2*>(g_Xg + (size_t)slot * DIM);
#pragma unroll
    for (int i = 0; i < 16; i++) {
        int c = lane + 32 * i;
        dst[c] = __float22half2_rn(src[c]);
    }
}

// ---------------- GEMM tiles (fp16, ldmatrix, 512 threads, BK=64) ------------
#define BM  128
#define BN  128
#define BK  64
#define BKP 72               // half row pad: 144B stride, conflict-free, 16B-aligned
#define NSTAGE 3
#define TILE_ST (128 * BKP)  // 9216 halfs per 128-row tile stage
#define G1_SMEM (NSTAGE * 3 * TILE_ST * 2)   // A + B1 + B3 = 165888 B
#define G2_SMEM (NSTAGE * 2 * TILE_ST * 2)   // A + B      = 110592 B

// GEMM1 fused: H = silu(Xg@W1 + b1) * (Xg@W3 + b3). 16 warps, warp tile 32x32.
__global__ __launch_bounds__(512, 1) void gemm1_kernel(
    const float* __restrict__ b1, const float* __restrict__ b3) {
    int e = g_tile_e[blockIdx.y];
    if (e < 0) return;
    int m0 = blockIdx.y * BM;
    int n0 = blockIdx.x * BN;

    const __half* A  = g_Xg  + (size_t)m0 * DIM;
    const __half* B1 = g_W1h + (size_t)e * INTER * DIM + (size_t)n0 * DIM;
    const __half* B3 = g_W3h + (size_t)e * INTER * DIM + (size_t)n0 * DIM;

    extern __shared__ __half sm[];
    __half* As  = sm;                        // [NSTAGE][128][BKP]
    __half* Bs1 = sm + NSTAGE * TILE_ST;     // [NSTAGE][128][BKP] (n-major)
    __half* Bs3 = Bs1 + NSTAGE * TILE_ST;

    int tid  = threadIdx.x;
    int lane = tid & 31, warp = tid >> 5;            // 0..15
    int wm = (warp >> 2) * 32, wn = (warp & 3) * 32; // 4x4 warp grid
    int g  = lane >> 2, tg = lane & 3;
    int rl = lane & 15, kh = (lane >> 4) * 8;

    float acc1[2][4][4] = {};
    float acc3[2][4][4] = {};

    const int KT = DIM / BK;   // 16

    auto load_stage = [&](int k0, int st) {
        __half* as  = As  + st * TILE_ST;
        __half* b1s = Bs1 + st * TILE_ST;
        __half* b3s = Bs3 + st * TILE_ST;
#pragma unroll
        for (int i = 0; i < 2; i++) {                // 128 rows x 64 halfs per buf
            int idx = tid + i * 512;
            int r = idx >> 3, ch = idx & 7;
            cp_async16(as  + r * BKP + ch * 8, A  + (size_t)r * DIM + k0 + ch * 8);
            cp_async16(b1s + r * BKP + ch * 8, B1 + (size_t)r * DIM + k0 + ch * 8);
            cp_async16(b3s + r * BKP + ch * 8, B3 + (size_t)r * DIM + k0 + ch * 8);
        }
    };

    load_stage(0, 0);  CP_COMMIT();
    load_stage(BK, 1); CP_COMMIT();

    for (int kt = 0; kt < KT; kt++) {
        CP_WAIT1();
        __syncthreads();
        int nk = kt + 2;
        if (nk < KT) load_stage(nk * BK, nk % NSTAGE);
        CP_COMMIT();

        int st = kt % NSTAGE;
        const __half* as  = As  + st * TILE_ST;
        const __half* b1s = Bs1 + st * TILE_ST;
        const __half* b3s = Bs3 + st * TILE_ST;
#pragma unroll
        for (int ks = 0; ks < BK; ks += 16) {
            uint32_t af[2][4];
#pragma unroll
            for (int mi = 0; mi < 2; mi++)
                ldm_x4(af[mi], smaddr(as + (wm + mi * 16 + rl) * BKP + ks + kh));
            uint32_t bf1[2][4], bf3[2][4];
#pragma unroll
            for (int nj = 0; nj < 2; nj++) {
                ldm_x4(bf1[nj], smaddr(b1s + (wn + nj * 16 + rl) * BKP + ks + kh));
                ldm_x4(bf3[nj], smaddr(b3s + (wn + nj * 16 + rl) * BKP + ks + kh));
            }
#pragma unroll
            for (int mi = 0; mi < 2; mi++) {
#pragma unroll
                for (int ni = 0; ni < 4; ni++) {
                    int nj = ni >> 1, p = ni & 1;
                    mma_f16(acc1[mi][ni], af[mi], bf1[nj][p], bf1[nj][2 + p]);
                    mma_f16(acc3[mi][ni], af[mi], bf3[nj][p], bf3[nj][2 + p]);
                }
            }
        }
    }

    // epilogue: bias + silu-glu, write H (fp16)
#pragma unroll
    for (int mi = 0; mi < 2; mi++) {
#pragma unroll
        for (int ni = 0; ni < 4; ni++) {
            int r0 = m0 + wm + mi * 16 + g;
            int cg = n0 + wn + ni * 8 + tg * 2;
            float b1a = __ldg(b1 + e * INTER + cg), b1b = __ldg(b1 + e * INTER + cg + 1);
            float b3a = __ldg(b3 + e * INTER + cg), b3b = __ldg(b3 + e * INTER + cg + 1);
            float h0 = silu_f(acc1[mi][ni][0] + b1a) * (acc3[mi][ni][0] + b3a);
            float h1 = silu_f(acc1[mi][ni][1] + b1b) * (acc3[mi][ni][1] + b3b);
            float h2 = silu_f(acc1[mi][ni][2] + b1a) * (acc3[mi][ni][2] + b3a);
            float h3 = silu_f(acc1[mi][ni][3] + b1b) * (acc3[mi][ni][3] + b3b);
            *reinterpret_cast<__half2*>(&g_H[(size_t)r0 * INTER + cg]) =
                __floats2half2_rn(h0, h1);
            *reinterpret_cast<__half2*>(&g_H[(size_t)(r0 + 8) * INTER + cg]) =
                __floats2half2_rn(h2, h3);
        }
    }
}

// GEMM2: O = H @ W2 + b2. 16 warps, warp tile 32x32.
__global__ __launch_bounds__(512, 1) void gemm2_kernel(const float* __restrict__ b2) {
    int e = g_tile_e[blockIdx.y];
    if (e < 0) return;
    int m0 = blockIdx.y * BM;
    int n0 = blockIdx.x * BN;

    const __half* A = g_H   + (size_t)m0 * INTER;
    const __half* B = g_W2h + (size_t)e * DIM * INTER + (size_t)n0 * INTER;

    extern __shared__ __half sm[];
    __half* As = sm;                        // [NSTAGE][128][BKP]
    __half* Bs = sm + NSTAGE * TILE_ST;     // [NSTAGE][128][BKP]

    int tid  = threadIdx.x;
    int lane = tid & 31, warp = tid >> 5;
    int wm = (warp >> 2) * 32, wn = (warp & 3) * 32;
    int g  = lane >> 2, tg = lane & 3;
    int rl = lane & 15, kh = (lane >> 4) * 8;

    float acc[2][4][4] = {};

    const int KT = INTER / BK;   // 32

    auto load_stage = [&](int k0, int st) {
        __half* as = As + st * TILE_ST;
        __half* bs = Bs + st * TILE_ST;
#pragma unroll
        for (int i = 0; i < 2; i++) {
            int idx = tid + i * 512;
            int r = idx >> 3, ch = idx & 7;
            cp_async16(as + r * BKP + ch * 8, A + (size_t)r * INTER + k0 + ch * 8);
            cp_async16(bs + r * BKP + ch * 8, B + (size_t)r * INTER + k0 + ch * 8);
        }
    };

    load_stage(0, 0);  CP_COMMIT();
    load_stage(BK, 1); CP_COMMIT();

    for (int kt = 0; kt < KT; kt++) {
        CP_WAIT1();
        __syncthreads();
        int nk = kt + 2;
        if (nk < KT) load_stage(nk * BK, nk % NSTAGE);
        CP_COMMIT();

        int st = kt % NSTAGE;
        const __half* as = As + st * TILE_ST;
        const __half* bs = Bs + st * TILE_ST;
#pragma unroll
        for (int ks = 0; ks < BK; ks += 16) {
            uint32_t af[2][4];
#pragma unroll
            for (int mi = 0; mi < 2; mi++)
                ldm_x4(af[mi], smaddr(as + (wm + mi * 16 + rl) * BKP + ks + kh));
            uint32_t bf[2][4];
#pragma unroll
            for (int nj = 0; nj < 2; nj++)
                ldm_x4(bf[nj], smaddr(bs + (wn + nj * 16 + rl) * BKP + ks + kh));
#pragma unroll
            for (int mi = 0; mi < 2; mi++) {
#pragma unroll
                for (int ni = 0; ni < 4; ni++) {
                    int nj = ni >> 1, p = ni & 1;
                    mma_f16(acc[mi][ni], af[mi], bf[nj][p], bf[nj][2 + p]);
                }
            }
        }
    }

#pragma unroll
    for (int mi = 0; mi < 2; mi++) {
#pragma unroll
        for (int ni = 0; ni < 4; ni++) {
            int r0 = m0 + wm + mi * 16 + g;
            int cg = n0 + wn + ni * 8 + tg * 2;
            float ba = __ldg(b2 + e * DIM + cg), bb = __ldg(b2 + e * DIM + cg + 1);
            *reinterpret_cast<float2*>(&g_O[(size_t)r0 * DIM + cg]) =
                make_float2(acc[mi][ni][0] + ba, acc[mi][ni][1] + bb);
            *reinterpret_cast<float2*>(&g_O[(size_t)(r0 + 8) * DIM + cg]) =
                make_float2(acc[mi][ni][2] + ba, acc[mi][ni][3] + bb);
        }
    }
}

// ---------------- combine (warp per token) -----------------------------------
__global__ void combine_kernel(float* __restrict__ y) {
    int t    = (blockIdx.x * blockDim.x + threadIdx.x) >> 5;
    int lane = threadIdx.x & 31;
    if (t >= T_TOK) return;
    int   s0 = g_tok_slot[2 * t],  s1 = g_tok_slot[2 * t + 1];
    float w0 = g_tok_w[2 * t],     w1 = g_tok_w[2 * t + 1];
    const float4* o0 = reinterpret_cast<const float4*>(g_O + (size_t)s0 * DIM);
    const float4* o1 = reinterpret_cast<const float4*>(g_O + (size_t)s1 * DIM);
    float4* yr = reinterpret_cast<float4*>(y + (size_t)t * DIM);
#pragma unroll
    for (int i = 0; i < 8; i++) {
        int c = lane + 32 * i;
        float4 a = o0[c], b = o1[c], r;
        r.x = w0 * a.x + w1 * b.x;
        r.y = w0 * a.y + w1 * b.y;
        r.z = w0 * a.z + w1 * b.z;
        r.w = w0 * a.w + w1 * b.w;
        yr[c] = r;
    }
}

// ---------------- launcher ---------------------------------------------------
extern "C" void kernel_launch(void* const* d_in, const int* in_sizes, int n_in,
                              void* d_out, int out_size) {
    const float* x  = (const float*)d_in[0];
    const float* Wg = (const float*)d_in[1];
    const float* bg = (const float*)d_in[2];
    const float* W1 = (const float*)d_in[3];
    const float* b1 = (const float*)d_in[4];
    const float* W2 = (const float*)d_in[5];
    const float* b2 = (const float*)d_in[6];
    const float* W3 = (const float*)d_in[7];
    const float* b3 = (const float*)d_in[8];
    float* y = (float*)d_out;

    cudaFuncSetAttribute(gemm1_kernel, cudaFuncAttributeMaxDynamicSharedMemorySize, G1_SMEM);
    cudaFuncSetAttribute(gemm2_kernel, cudaFuncAttributeMaxDynamicSharedMemorySize, G2_SMEM);

    // fp16 weight transposes: [e][n][k] (sel 0 also resets g_counts)
    convt_kernel<<<dim3(INTER / 32, DIM / 32, NEXP), dim3(32, 8)>>>(W1, 0, DIM, INTER);
    convt_kernel<<<dim3(INTER / 32, DIM / 32, NEXP), dim3(32, 8)>>>(W3, 1, DIM, INTER);
    convt_kernel<<<dim3(DIM / 32, INTER / 32, NEXP), dim3(32, 8)>>>(W2, 2, INTER, DIM);

    gate_kernel<<<T_TOK / 32, 256>>>(x, Wg, bg);
    offsets_kernel<<<1, 1>>>();
    assign_gather_kernel<<<NA / 8, 256>>>(x);
    gemm1_kernel<<<dim3(INTER / BN, NT_MAX), 512, G1_SMEM>>>(b1, b3);
    gemm2_kernel<<<dim3(DIM / BN, NT_MAX), 512, G2_SMEM>>>(b2);
    combine_kernel<<<T_TOK / 8, 256>>>(y);
}

// round 13
// speedup vs baseline: 1.3908x; 1.0087x over previous
#include <cuda_runtime.h>
#include <cuda_fp16.h>
#include <cstdint>

// Problem constants
#define T_TOK 8192
#define DIM   1024
#define NEXP  16
#define INTER 2048
#define NA    16384
#define NAP   18432
#define NT_MAX 144

// ---------------- static device scratch --------------------------------------
__device__ int    g_poff[NEXP];
__device__ int    g_cursor[NEXP];
__device__ int    g_tile_e[NT_MAX];
__device__ int    g_tok_e[NA];
__device__ float  g_tok_w[NA];
__device__ int    g_tok_slot[NA];
__device__ __half g_Xg[(size_t)NAP * DIM];            // gathered tokens (fp16)
__device__ __half g_H [(size_t)NAP * INTER];          // GLU hidden (fp16)
__device__ float  g_O [(size_t)NAP * DIM];            // expert outputs (fp32)
__device__ __half g_W1h[(size_t)NEXP * INTER * DIM];  // W1^T [e][n][k] fp16
__device__ __half g_W3h[(size_t)NEXP * INTER * DIM];  // W3^T [e][n][k]
__device__ __half g_W2h[(size_t)NEXP * DIM * INTER];  // W2^T [e][n][k]

// ---------------- helpers ----------------------------------------------------
__device__ __forceinline__ float silu_f(float x) { return x / (1.0f + __expf(-x)); }

__device__ __forceinline__ void cp_async16(void* smem_dst, const void* gmem_src) {
    uint32_t s = (uint32_t)__cvta_generic_to_shared(smem_dst);
    asm volatile("cp.async.cg.shared.global [%0], [%1], 16;\n" :: "r"(s), "l"(gmem_src));
}
#define CP_COMMIT() asm volatile("cp.async.commit_group;\n" ::: "memory")
#define CP_WAIT1()  asm volatile("cp.async.wait_group 1;\n" ::: "memory")

__device__ __forceinline__ uint32_t smaddr(const void* p) {
    return (uint32_t)__cvta_generic_to_shared(p);
}

__device__ __forceinline__ void ldm_x4(uint32_t* r, uint32_t addr) {
    asm volatile("ldmatrix.sync.aligned.m8n8.x4.shared.b16 {%0,%1,%2,%3}, [%4];"
                 : "=r"(r[0]), "=r"(r[1]), "=r"(r[2]), "=r"(r[3]) : "r"(addr));
}

// m16n8k16 fp16 mma, fp32 accumulate
__device__ __forceinline__ void mma_f16(float* d, const uint32_t* a,
                                        uint32_t b0, uint32_t b1) {
    asm volatile(
        "mma.sync.aligned.m16n8k16.row.col.f32.f16.f16.f32 "
        "{%0,%1,%2,%3},{%4,%5,%6,%7},{%8,%9},{%0,%1,%2,%3};\n"
        : "+f"(d[0]), "+f"(d[1]), "+f"(d[2]), "+f"(d[3])
        : "r"(a[0]), "r"(a[1]), "r"(a[2]), "r"(a[3]), "r"(b0), "r"(b1));
}

// ---------------- weight convert + transpose ([e][R][C]f32 -> [e][C][R]f16) --
__global__ void convt_kernel(const float* __restrict__ src, int sel, int R, int C) {
    __half* dst = (sel == 0) ? g_W1h : ((sel == 1) ? g_W3h : g_W2h);
    __shared__ float t[32][33];
    size_t base = (size_t)blockIdx.z * R * C;
    src += base; dst += base;
    int tx = threadIdx.x, ty = threadIdx.y;
    int x  = blockIdx.x * 32 + tx;
    int y0 = blockIdx.y * 32;
#pragma unroll
    for (int j = 0; j < 4; j++)
        t[ty + 8 * j][tx] = src[(size_t)(y0 + ty + 8 * j) * C + x];
    __syncthreads();
#pragma unroll
    for (int j = 0; j < 4; j++)
        dst[(size_t)(blockIdx.x * 32 + ty + 8 * j) * R + (y0 + tx)] =
            __float2half_rn(t[tx][ty + 8 * j]);
}

// ---------------- gate: 4 tokens per warp (no global atomics) ----------------
__global__ void gate_kernel(const float* __restrict__ x,
                            const float* __restrict__ Wg,
                            const float* __restrict__ bg) {
    int gw   = (blockIdx.x * blockDim.x + threadIdx.x) >> 5;
    int lane = threadIdx.x & 31;
    int t0   = gw * 4;
    if (t0 >= T_TOK) return;
    const float* x0 = x + (size_t)t0 * DIM;

    float acc[4][NEXP];
#pragma unroll
    for (int t = 0; t < 4; t++)
#pragma unroll
        for (int e = 0; e < NEXP; e++) acc[t][e] = 0.0f;

    for (int d = lane; d < DIM; d += 32) {
        const float4* w4 = reinterpret_cast<const float4*>(Wg + (size_t)d * NEXP);
        float4 w0 = w4[0], w1 = w4[1], w2 = w4[2], w3 = w4[3];
        float xv[4];
#pragma unroll
        for (int t = 0; t < 4; t++) xv[t] = __ldg(x0 + (size_t)t * DIM + d);
#pragma unroll
        for (int t = 0; t < 4; t++) {
            float v = xv[t];
            acc[t][0]  += v * w0.x; acc[t][1]  += v * w0.y;
            acc[t][2]  += v * w0.z; acc[t][3]  += v * w0.w;
            acc[t][4]  += v * w1.x; acc[t][5]  += v * w1.y;
            acc[t][6]  += v * w1.z; acc[t][7]  += v * w1.w;
            acc[t][8]  += v * w2.x; acc[t][9]  += v * w2.y;
            acc[t][10] += v * w2.z; acc[t][11] += v * w2.w;
            acc[t][12] += v * w3.x; acc[t][13] += v * w3.y;
            acc[t][14] += v * w3.z; acc[t][15] += v * w3.w;
        }
    }
#pragma unroll
    for (int t = 0; t < 4; t++)
#pragma unroll
        for (int e = 0; e < NEXP; e++) {
            float v = acc[t][e];
#pragma unroll
            for (int o = 16; o > 0; o >>= 1) v += __shfl_xor_sync(0xffffffffu, v, o);
            acc[t][e] = v;
        }
    if (lane < 4) {
        int t = t0 + lane;
        float fa[NEXP];
#pragma unroll
        for (int e = 0; e < NEXP; e++)
            fa[e] = (lane == 0) ? acc[0][e] : (lane == 1) ? acc[1][e]
                   : (lane == 2) ? acc[2][e] : acc[3][e];
        float l1 = -1e30f, l2 = -1e30f;
        int i1 = 0, i2 = 0;
#pragma unroll
        for (int e = 0; e < NEXP; e++) {
            float v = fa[e] + bg[e];
            if (v > l1) { l1 = v; i1 = e; }
        }
#pragma unroll
        for (int e = 0; e < NEXP; e++) {
            float v = fa[e] + bg[e];
            if (e != i1 && v > l2) { l2 = v; i2 = e; }
        }
        float e2 = __expf(l2 - l1);
        float w1v = 1.0f / (1.0f + e2);
        float w2v = e2 * w1v;
        g_tok_e[2 * t]     = i1;
        g_tok_e[2 * t + 1] = i2;
        g_tok_w[2 * t]     = w1v;
        g_tok_w[2 * t + 1] = w2v;
    }
}

// ---------------- offsets: histogram + padded prefix + tile map --------------
__global__ void offsets_kernel() {
    __shared__ int h[NEXP];
    int tid = threadIdx.x;
    if (tid < NEXP) h[tid] = 0;
    __syncthreads();
    for (int i = tid; i < NA; i += 256) atomicAdd(&h[g_tok_e[i]], 1);
    __syncthreads();
    if (tid == 0) {
        int run = 0, idx = 0;
        for (int e = 0; e < NEXP; e++) {
            g_poff[e]   = run;
            g_cursor[e] = 0;
            int pt = (h[e] + 127) >> 7;
            for (int i = 0; i < pt; i++) g_tile_e[idx++] = e;
            run += pt << 7;
        }
        for (; idx < NT_MAX; idx++) g_tile_e[idx] = -1;
    }
}

// ---------------- assign slots + gather (f32 -> fp16) ------------------------
__global__ void assign_gather_kernel(const float* __restrict__ x) {
    int aw   = (blockIdx.x * blockDim.x + threadIdx.x) >> 5;
    int lane = threadIdx.x & 31;
    if (aw >= NA) return;
    int t = aw >> 1;

    int slot = 0;
    if (lane == 0) {
        int e   = g_tok_e[aw];
        int pos = atomicAdd(&g_cursor[e], 1);
        slot    = g_poff[e] + pos;
        g_tok_slot[aw] = slot;
    }
    slot = __shfl_sync(0xffffffffu, slot, 0);

    const float2* src = reinterpret_cast<const float2*>(x + (size_t)t * DIM);
    __half2*      dst = reinterpret_cast<__half2*>(g_Xg + (size_t)slot * DIM);
#pragma unroll
    for (int i = 0; i < 16; i++) {
        int c = lane + 32 * i;
        dst[c] = __float22half2_rn(src[c]);
    }
}

// ---------------- GEMM tiles (fp16, ldmatrix, 512 threads, BK=64) ------------
#define BM  128
#define BN  128
#define BK  64
#define BKP 72               // half row pad: 144B stride, conflict-free, 16B-aligned
#define NSTAGE 3
#define TILE_ST (128 * BKP)  // 9216 halfs per 128-row tile stage
#define G1_SMEM (NSTAGE * 3 * TILE_ST * 2)   // A + B1 + B3 = 165888 B
#define G2_SMEM (NSTAGE * 2 * TILE_ST * 2)   // A + B      = 110592 B

// GEMM1 fused: H = silu(Xg@W1 + b1) * (Xg@W3 + b3). 16 warps, warp tile 32x32.
__global__ __launch_bounds__(512, 1) void gemm1_kernel(
    const float* __restrict__ b1, const float* __restrict__ b3) {
    int e = g_tile_e[blockIdx.y];
    if (e < 0) return;
    int m0 = blockIdx.y * BM;
    int n0 = blockIdx.x * BN;

    const __half* A  = g_Xg  + (size_t)m0 * DIM;
    const __half* B1 = g_W1h + (size_t)e * INTER * DIM + (size_t)n0 * DIM;
    const __half* B3 = g_W3h + (size_t)e * INTER * DIM + (size_t)n0 * DIM;

    extern __shared__ __half sm[];
    __half* As  = sm;                        // [NSTAGE][128][BKP]
    __half* Bs1 = sm + NSTAGE * TILE_ST;     // [NSTAGE][128][BKP] (n-major)
    __half* Bs3 = Bs1 + NSTAGE * TILE_ST;

    int tid  = threadIdx.x;
    int lane = tid & 31, warp = tid >> 5;            // 0..15
    int wm = (warp >> 2) * 32, wn = (warp & 3) * 32; // 4x4 warp grid
    int g  = lane >> 2, tg = lane & 3;
    int rl = lane & 15, kh = (lane >> 4) * 8;

    float acc1[2][4][4] = {};
    float acc3[2][4][4] = {};

    const int KT = DIM / BK;   // 16

    auto load_stage = [&](int k0, int st) {
        __half* as  = As  + st * TILE_ST;
        __half* b1s = Bs1 + st * TILE_ST;
        __half* b3s = Bs3 + st * TILE_ST;
#pragma unroll
        for (int i = 0; i < 2; i++) {                // 128 rows x 64 halfs per buf
            int idx = tid + i * 512;
            int r = idx >> 3, ch = idx & 7;
            cp_async16(as  + r * BKP + ch * 8, A  + (size_t)r * DIM + k0 + ch * 8);
            cp_async16(b1s + r * BKP + ch * 8, B1 + (size_t)r * DIM + k0 + ch * 8);
            cp_async16(b3s + r * BKP + ch * 8, B3 + (size_t)r * DIM + k0 + ch * 8);
        }
    };

    load_stage(0, 0);  CP_COMMIT();
    load_stage(BK, 1); CP_COMMIT();

    for (int kt = 0; kt < KT; kt++) {
        CP_WAIT1();
        __syncthreads();
        int nk = kt + 2;
        if (nk < KT) load_stage(nk * BK, nk % NSTAGE);
        CP_COMMIT();

        int st = kt % NSTAGE;
        const __half* as  = As  + st * TILE_ST;
        const __half* b1s = Bs1 + st * TILE_ST;
        const __half* b3s = Bs3 + st * TILE_ST;
#pragma unroll
        for (int ks = 0; ks < BK; ks += 16) {
            uint32_t af[2][4];
#pragma unroll
            for (int mi = 0; mi < 2; mi++)
                ldm_x4(af[mi], smaddr(as + (wm + mi * 16 + rl) * BKP + ks + kh));
            uint32_t bf1[2][4], bf3[2][4];
#pragma unroll
            for (int nj = 0; nj < 2; nj++) {
                ldm_x4(bf1[nj], smaddr(b1s + (wn + nj * 16 + rl) * BKP + ks + kh));
                ldm_x4(bf3[nj], smaddr(b3s + (wn + nj * 16 + rl) * BKP + ks + kh));
            }
#pragma unroll
            for (int mi = 0; mi < 2; mi++) {
#pragma unroll
                for (int ni = 0; ni < 4; ni++) {
                    int nj = ni >> 1, p = ni & 1;
                    mma_f16(acc1[mi][ni], af[mi], bf1[nj][p], bf1[nj][2 + p]);
                    mma_f16(acc3[mi][ni], af[mi], bf3[nj][p], bf3[nj][2 + p]);
                }
            }
        }
    }

    // epilogue: bias + silu-glu, write H (fp16)
#pragma unroll
    for (int mi = 0; mi < 2; mi++) {
#pragma unroll
        for (int ni = 0; ni < 4; ni++) {
            int r0 = m0 + wm + mi * 16 + g;
            int cg = n0 + wn + ni * 8 + tg * 2;
            float b1a = __ldg(b1 + e * INTER + cg), b1b = __ldg(b1 + e * INTER + cg + 1);
            float b3a = __ldg(b3 + e * INTER + cg), b3b = __ldg(b3 + e * INTER + cg + 1);
            float h0 = silu_f(acc1[mi][ni][0] + b1a) * (acc3[mi][ni][0] + b3a);
            float h1 = silu_f(acc1[mi][ni][1] + b1b) * (acc3[mi][ni][1] + b3b);
            float h2 = silu_f(acc1[mi][ni][2] + b1a) * (acc3[mi][ni][2] + b3a);
            float h3 = silu_f(acc1[mi][ni][3] + b1b) * (acc3[mi][ni][3] + b3b);
            *reinterpret_cast<__half2*>(&g_H[(size_t)r0 * INTER + cg]) =
                __floats2half2_rn(h0, h1);
            *reinterpret_cast<__half2*>(&g_H[(size_t)(r0 + 8) * INTER + cg]) =
                __floats2half2_rn(h2, h3);
        }
    }
}

// GEMM2: O = H @ W2 + b2. 16 warps, warp tile 32x32.
__global__ __launch_bounds__(512, 1) void gemm2_kernel(const float* __restrict__ b2) {
    int e = g_tile_e[blockIdx.y];
    if (e < 0) return;
    int m0 = blockIdx.y * BM;
    int n0 = blockIdx.x * BN;

    const __half* A = g_H   + (size_t)m0 * INTER;
    const __half* B = g_W2h + (size_t)e * DIM * INTER + (size_t)n0 * INTER;

    extern __shared__ __half sm[];
    __half* As = sm;                        // [NSTAGE][128][BKP]
    __half* Bs = sm + NSTAGE * TILE_ST;     // [NSTAGE][128][BKP]

    int tid  = threadIdx.x;
    int lane = tid & 31, warp = tid >> 5;
    int wm = (warp >> 2) * 32, wn = (warp & 3) * 32;
    int g  = lane >> 2, tg = lane & 3;
    int rl = lane & 15, kh = (lane >> 4) * 8;

    float acc[2][4][4] = {};

    const int KT = INTER / BK;   // 32

    auto load_stage = [&](int k0, int st) {
        __half* as = As + st * TILE_ST;
        __half* bs = Bs + st * TILE_ST;
#pragma unroll
        for (int i = 0; i < 2; i++) {
            int idx = tid + i * 512;
            int r = idx >> 3, ch = idx & 7;
            cp_async16(as + r * BKP + ch * 8, A + (size_t)r * INTER + k0 + ch * 8);
            cp_async16(bs + r * BKP + ch * 8, B + (size_t)r * INTER + k0 + ch * 8);
        }
    };

    load_stage(0, 0);  CP_COMMIT();
    load_stage(BK, 1); CP_COMMIT();

    for (int kt = 0; kt < KT; kt++) {
        CP_WAIT1();
        __syncthreads();
        int nk = kt + 2;
        if (nk < KT) load_stage(nk * BK, nk % NSTAGE);
        CP_COMMIT();

        int st = kt % NSTAGE;
        const __half* as = As + st * TILE_ST;
        const __half* bs = Bs + st * TILE_ST;
#pragma unroll
        for (int ks = 0; ks < BK; ks += 16) {
            uint32_t af[2][4];
#pragma unroll
            for (int mi = 0; mi < 2; mi++)
                ldm_x4(af[mi], smaddr(as + (wm + mi * 16 + rl) * BKP + ks + kh));
            uint32_t bf[2][4];
#pragma unroll
            for (int nj = 0; nj < 2; nj++)
                ldm_x4(bf[nj], smaddr(bs + (wn + nj * 16 + rl) * BKP + ks + kh));
#pragma unroll
            for (int mi = 0; mi < 2; mi++) {
#pragma unroll
                for (int ni = 0; ni < 4; ni++) {
                    int nj = ni >> 1, p = ni & 1;
                    mma_f16(acc[mi][ni], af[mi], bf[nj][p], bf[nj][2 + p]);
                }
            }
        }
    }

#pragma unroll
    for (int mi = 0; mi < 2; mi++) {
#pragma unroll
        for (int ni = 0; ni < 4; ni++) {
            int r0 = m0 + wm + mi * 16 + g;
            int cg = n0 + wn + ni * 8 + tg * 2;
            float ba = __ldg(b2 + e * DIM + cg), bb = __ldg(b2 + e * DIM + cg + 1);
            *reinterpret_cast<float2*>(&g_O[(size_t)r0 * DIM + cg]) =
                make_float2(acc[mi][ni][0] + ba, acc[mi][ni][1] + bb);
            *reinterpret_cast<float2*>(&g_O[(size_t)(r0 + 8) * DIM + cg]) =
                make_float2(acc[mi][ni][2] + ba, acc[mi][ni][3] + bb);
        }
    }
}

// ---------------- combine (warp per token) -----------------------------------
__global__ void combine_kernel(float* __restrict__ y) {
    int t    = (blockIdx.x * blockDim.x + threadIdx.x) >> 5;
    int lane = threadIdx.x & 31;
    if (t >= T_TOK) return;
    int   s0 = g_tok_slot[2 * t],  s1 = g_tok_slot[2 * t + 1];
    float w0 = g_tok_w[2 * t],     w1 = g_tok_w[2 * t + 1];
    const float4* o0 = reinterpret_cast<const float4*>(g_O + (size_t)s0 * DIM);
    const float4* o1 = reinterpret_cast<const float4*>(g_O + (size_t)s1 * DIM);
    float4* yr = reinterpret_cast<float4*>(y + (size_t)t * DIM);
#pragma unroll
    for (int i = 0; i < 8; i++) {
        int c = lane + 32 * i;
        float4 a = o0[c], b = o1[c], r;
        r.x = w0 * a.x + w1 * b.x;
        r.y = w0 * a.y + w1 * b.y;
        r.z = w0 * a.z + w1 * b.z;
        r.w = w0 * a.w + w1 * b.w;
        yr[c] = r;
    }
}

// ---------------- launcher ---------------------------------------------------
extern "C" void kernel_launch(void* const* d_in, const int* in_sizes, int n_in,
                              void* d_out, int out_size) {
    const float* x  = (const float*)d_in[0];
    const float* Wg = (const float*)d_in[1];
    const float* bg = (const float*)d_in[2];
    const float* W1 = (const float*)d_in[3];
    const float* b1 = (const float*)d_in[4];
    const float* W2 = (const float*)d_in[5];
    const float* b2 = (const float*)d_in[6];
    const float* W3 = (const float*)d_in[7];
    const float* b3 = (const float*)d_in[8];
    float* y = (float*)d_out;

    // Side streams/events: created once on the first (non-captured) call.
    // Every call performs identical launches; only handle creation is one-time.
    static cudaStream_t s1 = nullptr, s2 = nullptr;
    static cudaEvent_t  evF = nullptr, ev1 = nullptr, ev2 = nullptr;
    if (s1 == nullptr) {
        cudaStreamCreateWithFlags(&s1, cudaStreamNonBlocking);
        cudaStreamCreateWithFlags(&s2, cudaStreamNonBlocking);
        cudaEventCreateWithFlags(&evF, cudaEventDisableTiming);
        cudaEventCreateWithFlags(&ev1, cudaEventDisableTiming);
        cudaEventCreateWithFlags(&ev2, cudaEventDisableTiming);
        cudaFuncSetAttribute(gemm1_kernel, cudaFuncAttributeMaxDynamicSharedMemorySize, G1_SMEM);
        cudaFuncSetAttribute(gemm2_kernel, cudaFuncAttributeMaxDynamicSharedMemorySize, G2_SMEM);
    }

    // Fork: weight transposes on side streams, routing on the main stream.
    cudaEventRecord(evF, 0);
    cudaStreamWaitEvent(s1, evF, 0);
    cudaStreamWaitEvent(s2, evF, 0);

    convt_kernel<<<dim3(INTER / 32, DIM / 32, NEXP), dim3(32, 8), 0, s1>>>(W1, 0, DIM, INTER);
    convt_kernel<<<dim3(INTER / 32, DIM / 32, NEXP), dim3(32, 8), 0, s1>>>(W3, 1, DIM, INTER);
    cudaEventRecord(ev1, s1);

    convt_kernel<<<dim3(DIM / 32, INTER / 32, NEXP), dim3(32, 8), 0, s2>>>(W2, 2, INTER, DIM);
    cudaEventRecord(ev2, s2);

    gate_kernel<<<T_TOK / 32, 256>>>(x, Wg, bg);
    offsets_kernel<<<1, 256>>>();
    assign_gather_kernel<<<NA / 8, 256>>>(x);

    cudaStreamWaitEvent(0, ev1, 0);   // W1/W3 ready
    gemm1_kernel<<<dim3(INTER / BN, NT_MAX), 512, G1_SMEM>>>(b1, b3);
    cudaStreamWaitEvent(0, ev2, 0);   // W2 ready (normally long done)
    gemm2_kernel<<<dim3(DIM / BN, NT_MAX), 512, G2_SMEM>>>(b2);
    combine_kernel<<<T_TOK / 8, 256>>>(y);
}

// round 14
// speedup vs baseline: 1.4610x; 1.0505x over previous
#include <cuda_runtime.h>
#include <cuda_fp16.h>
#include <cstdint>

// Problem constants
#define T_TOK 8192
#define DIM   1024
#define NEXP  16
#define INTER 2048
#define NA    16384
#define NAP   18432
#define NT_MAX 144

// ---------------- static device scratch --------------------------------------
__device__ int    g_poff[NEXP];
__device__ int    g_cursor[NEXP];
__device__ int    g_tile_e[NT_MAX];
__device__ int    g_tok_e[NA];
__device__ float  g_tok_w[NA];
__device__ int    g_tok_slot[NA];
__device__ __half g_Xg[(size_t)NAP * DIM];            // gathered tokens (fp16)
__device__ __half g_H [(size_t)NAP * INTER];          // GLU hidden (fp16)
__device__ float  g_O [(size_t)NAP * DIM];            // expert outputs (fp32)
__device__ __half g_W1h[(size_t)NEXP * INTER * DIM];  // W1^T [e][n][k] fp16
__device__ __half g_W3h[(size_t)NEXP * INTER * DIM];  // W3^T [e][n][k]
__device__ __half g_W2h[(size_t)NEXP * DIM * INTER];  // W2^T [e][n][k]

// ---------------- helpers ----------------------------------------------------
__device__ __forceinline__ float silu_f(float x) { return x / (1.0f + __expf(-x)); }

__device__ __forceinline__ void cp_async16s(uint32_t smem_dst, const void* gmem_src) {
    asm volatile("cp.async.cg.shared.global [%0], [%1], 16;\n" :: "r"(smem_dst), "l"(gmem_src));
}
#define CP_COMMIT() asm volatile("cp.async.commit_group;\n" ::: "memory")
#define CP_WAIT1()  asm volatile("cp.async.wait_group 1;\n" ::: "memory")

__device__ __forceinline__ uint32_t smaddr(const void* p) {
    return (uint32_t)__cvta_generic_to_shared(p);
}

__device__ __forceinline__ void ldm_x4(uint32_t* r, uint32_t addr) {
    asm volatile("ldmatrix.sync.aligned.m8n8.x4.shared.b16 {%0,%1,%2,%3}, [%4];"
                 : "=r"(r[0]), "=r"(r[1]), "=r"(r[2]), "=r"(r[3]) : "r"(addr));
}

// m16n8k16 fp16 mma, fp32 accumulate
__device__ __forceinline__ void mma_f16(float* d, const uint32_t* a,
                                        uint32_t b0, uint32_t b1) {
    asm volatile(
        "mma.sync.aligned.m16n8k16.row.col.f32.f16.f16.f32 "
        "{%0,%1,%2,%3},{%4,%5,%6,%7},{%8,%9},{%0,%1,%2,%3};\n"
        : "+f"(d[0]), "+f"(d[1]), "+f"(d[2]), "+f"(d[3])
        : "r"(a[0]), "r"(a[1]), "r"(a[2]), "r"(a[3]), "r"(b0), "r"(b1));
}

// ---------------- weight convert + transpose ([e][R][C]f32 -> [e][C][R]f16) --
__global__ void convt_kernel(const float* __restrict__ src, int sel, int R, int C) {
    __half* dst = (sel == 0) ? g_W1h : ((sel == 1) ? g_W3h : g_W2h);
    __shared__ float t[32][33];
    size_t base = (size_t)blockIdx.z * R * C;
    src += base; dst += base;
    int tx = threadIdx.x, ty = threadIdx.y;
    int x  = blockIdx.x * 32 + tx;
    int y0 = blockIdx.y * 32;
#pragma unroll
    for (int j = 0; j < 4; j++)
        t[ty + 8 * j][tx] = src[(size_t)(y0 + ty + 8 * j) * C + x];
    __syncthreads();
#pragma unroll
    for (int j = 0; j < 4; j++)
        dst[(size_t)(blockIdx.x * 32 + ty + 8 * j) * R + (y0 + tx)] =
            __float2half_rn(t[tx][ty + 8 * j]);
}

// ---------------- gate: 4 tokens per warp (no global atomics) ----------------
__global__ void gate_kernel(const float* __restrict__ x,
                            const float* __restrict__ Wg,
                            const float* __restrict__ bg) {
    int gw   = (blockIdx.x * blockDim.x + threadIdx.x) >> 5;
    int lane = threadIdx.x & 31;
    int t0   = gw * 4;
    if (t0 >= T_TOK) return;
    const float* x0 = x + (size_t)t0 * DIM;

    float acc[4][NEXP];
#pragma unroll
    for (int t = 0; t < 4; t++)
#pragma unroll
        for (int e = 0; e < NEXP; e++) acc[t][e] = 0.0f;

    for (int d = lane; d < DIM; d += 32) {
        const float4* w4 = reinterpret_cast<const float4*>(Wg + (size_t)d * NEXP);
        float4 w0 = w4[0], w1 = w4[1], w2 = w4[2], w3 = w4[3];
        float xv[4];
#pragma unroll
        for (int t = 0; t < 4; t++) xv[t] = __ldg(x0 + (size_t)t * DIM + d);
#pragma unroll
        for (int t = 0; t < 4; t++) {
            float v = xv[t];
            acc[t][0]  += v * w0.x; acc[t][1]  += v * w0.y;
            acc[t][2]  += v * w0.z; acc[t][3]  += v * w0.w;
            acc[t][4]  += v * w1.x; acc[t][5]  += v * w1.y;
            acc[t][6]  += v * w1.z; acc[t][7]  += v * w1.w;
            acc[t][8]  += v * w2.x; acc[t][9]  += v * w2.y;
            acc[t][10] += v * w2.z; acc[t][11] += v * w2.w;
            acc[t][12] += v * w3.x; acc[t][13] += v * w3.y;
            acc[t][14] += v * w3.z; acc[t][15] += v * w3.w;
        }
    }
#pragma unroll
    for (int t = 0; t < 4; t++)
#pragma unroll
        for (int e = 0; e < NEXP; e++) {
            float v = acc[t][e];
#pragma unroll
            for (int o = 16; o > 0; o >>= 1) v += __shfl_xor_sync(0xffffffffu, v, o);
            acc[t][e] = v;
        }
    if (lane < 4) {
        int t = t0 + lane;
        float fa[NEXP];
#pragma unroll
        for (int e = 0; e < NEXP; e++)
            fa[e] = (lane == 0) ? acc[0][e] : (lane == 1) ? acc[1][e]
                   : (lane == 2) ? acc[2][e] : acc[3][e];
        float l1 = -1e30f, l2 = -1e30f;
        int i1 = 0, i2 = 0;
#pragma unroll
        for (int e = 0; e < NEXP; e++) {
            float v = fa[e] + bg[e];
            if (v > l1) { l1 = v; i1 = e; }
        }
#pragma unroll
        for (int e = 0; e < NEXP; e++) {
            float v = fa[e] + bg[e];
            if (e != i1 && v > l2) { l2 = v; i2 = e; }
        }
        float e2 = __expf(l2 - l1);
        float w1v = 1.0f / (1.0f + e2);
        float w2v = e2 * w1v;
        g_tok_e[2 * t]     = i1;
        g_tok_e[2 * t + 1] = i2;
        g_tok_w[2 * t]     = w1v;
        g_tok_w[2 * t + 1] = w2v;
    }
}

// ---------------- offsets: histogram + padded prefix + tile map --------------
__global__ void offsets_kernel() {
    __shared__ int h[NEXP];
    int tid = threadIdx.x;
    if (tid < NEXP) h[tid] = 0;
    __syncthreads();
    for (int i = tid; i < NA; i += 256) atomicAdd(&h[g_tok_e[i]], 1);
    __syncthreads();
    if (tid == 0) {
        int run = 0, idx = 0;
        for (int e = 0; e < NEXP; e++) {
            g_poff[e]   = run;
            g_cursor[e] = 0;
            int pt = (h[e] + 127) >> 7;
            for (int i = 0; i < pt; i++) g_tile_e[idx++] = e;
            run += pt << 7;
        }
        for (; idx < NT_MAX; idx++) g_tile_e[idx] = -1;
    }
}

// ---------------- assign slots + gather (f32 -> fp16) ------------------------
__global__ void assign_gather_kernel(const float* __restrict__ x) {
    int aw   = (blockIdx.x * blockDim.x + threadIdx.x) >> 5;
    int lane = threadIdx.x & 31;
    if (aw >= NA) return;
    int t = aw >> 1;

    int slot = 0;
    if (lane == 0) {
        int e   = g_tok_e[aw];
        int pos = atomicAdd(&g_cursor[e], 1);
        slot    = g_poff[e] + pos;
        g_tok_slot[aw] = slot;
    }
    slot = __shfl_sync(0xffffffffu, slot, 0);

    const float2* src = reinterpret_cast<const float2*>(x + (size_t)t * DIM);
    __half2*      dst = reinterpret_cast<__half2*>(g_Xg + (size_t)slot * DIM);
#pragma unroll
    for (int i = 0; i < 16; i++) {
        int c = lane + 32 * i;
        dst[c] = __float22half2_rn(src[c]);
    }
}

// ---------------- GEMM tiles (fp16, ldmatrix, 512 threads, BK=64) ------------
#define BM  128
#define BN  128
#define BK  64
#define BKP 72               // half row pad: 144B stride, conflict-free, 16B-aligned
#define NSTAGE 3
#define TILE_ST (128 * BKP)  // 9216 halfs per 128-row tile stage
#define ST_B   (TILE_ST * 2) // stage stride in bytes (18432)
#define MI_B   (16 * BKP * 2)// 16-row step in bytes
#define G1_SMEM (NSTAGE * 3 * TILE_ST * 2)   // A + B1 + B3 = 165888 B
#define G2_SMEM (NSTAGE * 2 * TILE_ST * 2)   // A + B      = 110592 B

// GEMM1 fused: H = silu(Xg@W1 + b1) * (Xg@W3 + b3). 16 warps, warp tile 32x32.
__global__ __launch_bounds__(512, 1) void gemm1_kernel(
    const float* __restrict__ b1, const float* __restrict__ b3) {
    int e = g_tile_e[blockIdx.y];
    if (e < 0) return;
    int m0 = blockIdx.y * BM;
    int n0 = blockIdx.x * BN;

    const __half* A  = g_Xg  + (size_t)m0 * DIM;
    const __half* B1 = g_W1h + (size_t)e * INTER * DIM + (size_t)n0 * DIM;
    const __half* B3 = g_W3h + (size_t)e * INTER * DIM + (size_t)n0 * DIM;

    extern __shared__ __half sm[];
    __half* As  = sm;                        // [NSTAGE][128][BKP]
    __half* Bs1 = sm + NSTAGE * TILE_ST;     // [NSTAGE][128][BKP] (n-major)
    __half* Bs3 = Bs1 + NSTAGE * TILE_ST;

    int tid  = threadIdx.x;
    int lane = tid & 31, warp = tid >> 5;            // 0..15
    int wm = (warp >> 2) * 32, wn = (warp & 3) * 32; // 4x4 warp grid
    int g  = lane >> 2, tg = lane & 3;
    int rl = lane & 15, kh = (lane >> 4) * 8;

    // --- precomputed ldmatrix base addresses (bytes) ---
    uint32_t aB  = smaddr(As)  + 2u * ((wm + rl) * BKP + kh);
    uint32_t b1B = smaddr(Bs1) + 2u * ((wn + rl) * BKP + kh);
    uint32_t b3B = smaddr(Bs3) + 2u * ((wn + rl) * BKP + kh);

    // --- precomputed cp.async src/dst (2 chunks per buffer) ---
    int r1 = tid >> 3, ch = tid & 7;
    const __half* sA0 = A  + (size_t)r1 * DIM + ch * 8;
    const __half* sA1 = sA0 + (size_t)64 * DIM;
    const __half* s10 = B1 + (size_t)r1 * DIM + ch * 8;
    const __half* s11 = s10 + (size_t)64 * DIM;
    const __half* s30 = B3 + (size_t)r1 * DIM + ch * 8;
    const __half* s31 = s30 + (size_t)64 * DIM;
    uint32_t dA0 = smaddr(As)  + 2u * (r1 * BKP + ch * 8);
    uint32_t dA1 = dA0 + (uint32_t)(64 * BKP * 2);
    uint32_t d10 = smaddr(Bs1) + 2u * (r1 * BKP + ch * 8);
    uint32_t d11 = d10 + (uint32_t)(64 * BKP * 2);
    uint32_t d30 = smaddr(Bs3) + 2u * (r1 * BKP + ch * 8);
    uint32_t d31 = d30 + (uint32_t)(64 * BKP * 2);

    float acc1[2][4][4] = {};
    float acc3[2][4][4] = {};

    const int KT = DIM / BK;   // 16

    auto load = [&](int k0, uint32_t off) {
        cp_async16s(dA0 + off, sA0 + k0);
        cp_async16s(dA1 + off, sA1 + k0);
        cp_async16s(d10 + off, s10 + k0);
        cp_async16s(d11 + off, s11 + k0);
        cp_async16s(d30 + off, s30 + k0);
        cp_async16s(d31 + off, s31 + k0);
    };

    load(0, 0);       CP_COMMIT();
    load(BK, ST_B);   CP_COMMIT();

    uint32_t stOff = 0;          // stage being consumed (bytes)
    uint32_t ldOff = 2 * ST_B;   // stage being loaded (bytes)
    for (int kt = 0; kt < KT; kt++) {
        CP_WAIT1();
        __syncthreads();
        int nk = kt + 2;
        if (nk < KT) load(nk * BK, ldOff);
        CP_COMMIT();
        ldOff += ST_B; if (ldOff == 3 * ST_B) ldOff = 0;

        uint32_t aS = aB + stOff, b1S = b1B + stOff, b3S = b3B + stOff;
#pragma unroll
        for (int ks = 0; ks < BK; ks += 16) {
            uint32_t ko = (uint32_t)(2 * ks);
            uint32_t af[2][4];
            ldm_x4(af[0], aS + ko);
            ldm_x4(af[1], aS + MI_B + ko);
            uint32_t bf1[2][4], bf3[2][4];
            ldm_x4(bf1[0], b1S + ko);
            ldm_x4(bf1[1], b1S + MI_B + ko);
            ldm_x4(bf3[0], b3S + ko);
            ldm_x4(bf3[1], b3S + MI_B + ko);
#pragma unroll
            for (int mi = 0; mi < 2; mi++) {
#pragma unroll
                for (int ni = 0; ni < 4; ni++) {
                    int nj = ni >> 1, p = ni & 1;
                    mma_f16(acc1[mi][ni], af[mi], bf1[nj][p], bf1[nj][2 + p]);
                    mma_f16(acc3[mi][ni], af[mi], bf3[nj][p], bf3[nj][2 + p]);
                }
            }
        }
        stOff += ST_B; if (stOff == 3 * ST_B) stOff = 0;
    }

    // epilogue: bias + silu-glu, write H (fp16)
#pragma unroll
    for (int mi = 0; mi < 2; mi++) {
#pragma unroll
        for (int ni = 0; ni < 4; ni++) {
            int r0 = m0 + wm + mi * 16 + g;
            int cg = n0 + wn + ni * 8 + tg * 2;
            float b1a = __ldg(b1 + e * INTER + cg), b1b = __ldg(b1 + e * INTER + cg + 1);
            float b3a = __ldg(b3 + e * INTER + cg), b3b = __ldg(b3 + e * INTER + cg + 1);
            float h0 = silu_f(acc1[mi][ni][0] + b1a) * (acc3[mi][ni][0] + b3a);
            float h1 = silu_f(acc1[mi][ni][1] + b1b) * (acc3[mi][ni][1] + b3b);
            float h2 = silu_f(acc1[mi][ni][2] + b1a) * (acc3[mi][ni][2] + b3a);
            float h3 = silu_f(acc1[mi][ni][3] + b1b) * (acc3[mi][ni][3] + b3b);
            *reinterpret_cast<__half2*>(&g_H[(size_t)r0 * INTER + cg]) =
                __floats2half2_rn(h0, h1);
            *reinterpret_cast<__half2*>(&g_H[(size_t)(r0 + 8) * INTER + cg]) =
                __floats2half2_rn(h2, h3);
        }
    }
}

// GEMM2: O = H @ W2 + b2. 16 warps, warp tile 32x32.
__global__ __launch_bounds__(512, 1) void gemm2_kernel(const float* __restrict__ b2) {
    int e = g_tile_e[blockIdx.y];
    if (e < 0) return;
    int m0 = blockIdx.y * BM;
    int n0 = blockIdx.x * BN;

    const __half* A = g_H   + (size_t)m0 * INTER;
    const __half* B = g_W2h + (size_t)e * DIM * INTER + (size_t)n0 * INTER;

    extern __shared__ __half sm[];
    __half* As = sm;                        // [NSTAGE][128][BKP]
    __half* Bs = sm + NSTAGE * TILE_ST;     // [NSTAGE][128][BKP]

    int tid  = threadIdx.x;
    int lane = tid & 31, warp = tid >> 5;
    int wm = (warp >> 2) * 32, wn = (warp & 3) * 32;
    int g  = lane >> 2, tg = lane & 3;
    int rl = lane & 15, kh = (lane >> 4) * 8;

    uint32_t aB = smaddr(As) + 2u * ((wm + rl) * BKP + kh);
    uint32_t bB = smaddr(Bs) + 2u * ((wn + rl) * BKP + kh);

    int r1 = tid >> 3, ch = tid & 7;
    const __half* sA0 = A + (size_t)r1 * INTER + ch * 8;
    const __half* sA1 = sA0 + (size_t)64 * INTER;
    const __half* sB0 = B + (size_t)r1 * INTER + ch * 8;
    const __half* sB1 = sB0 + (size_t)64 * INTER;
    uint32_t dA0 = smaddr(As) + 2u * (r1 * BKP + ch * 8);
    uint32_t dA1 = dA0 + (uint32_t)(64 * BKP * 2);
    uint32_t dB0 = smaddr(Bs) + 2u * (r1 * BKP + ch * 8);
    uint32_t dB1 = dB0 + (uint32_t)(64 * BKP * 2);

    float acc[2][4][4] = {};

    const int KT = INTER / BK;   // 32

    auto load = [&](int k0, uint32_t off) {
        cp_async16s(dA0 + off, sA0 + k0);
        cp_async16s(dA1 + off, sA1 + k0);
        cp_async16s(dB0 + off, sB0 + k0);
        cp_async16s(dB1 + off, sB1 + k0);
    };

    load(0, 0);     CP_COMMIT();
    load(BK, ST_B); CP_COMMIT();

    uint32_t stOff = 0;
    uint32_t ldOff = 2 * ST_B;
    for (int kt = 0; kt < KT; kt++) {
        CP_WAIT1();
        __syncthreads();
        int nk = kt + 2;
        if (nk < KT) load(nk * BK, ldOff);
        CP_COMMIT();
        ldOff += ST_B; if (ldOff == 3 * ST_B) ldOff = 0;

        uint32_t aS = aB + stOff, bS = bB + stOff;
#pragma unroll
        for (int ks = 0; ks < BK; ks += 16) {
            uint32_t ko = (uint32_t)(2 * ks);
            uint32_t af[2][4];
            ldm_x4(af[0], aS + ko);
            ldm_x4(af[1], aS + MI_B + ko);
            uint32_t bf[2][4];
            ldm_x4(bf[0], bS + ko);
            ldm_x4(bf[1], bS + MI_B + ko);
#pragma unroll
            for (int mi = 0; mi < 2; mi++) {
#pragma unroll
                for (int ni = 0; ni < 4; ni++) {
                    int nj = ni >> 1, p = ni & 1;
                    mma_f16(acc[mi][ni], af[mi], bf[nj][p], bf[nj][2 + p]);
                }
            }
        }
        stOff += ST_B; if (stOff == 3 * ST_B) stOff = 0;
    }

#pragma unroll
    for (int mi = 0; mi < 2; mi++) {
#pragma unroll
        for (int ni = 0; ni < 4; ni++) {
            int r0 = m0 + wm + mi * 16 + g;
            int cg = n0 + wn + ni * 8 + tg * 2;
            float ba = __ldg(b2 + e * DIM + cg), bb = __ldg(b2 + e * DIM + cg + 1);
            *reinterpret_cast<float2*>(&g_O[(size_t)r0 * DIM + cg]) =
                make_float2(acc[mi][ni][0] + ba, acc[mi][ni][1] + bb);
            *reinterpret_cast<float2*>(&g_O[(size_t)(r0 + 8) * DIM + cg]) =
                make_float2(acc[mi][ni][2] + ba, acc[mi][ni][3] + bb);
        }
    }
}

// ---------------- combine (warp per token) -----------------------------------
__global__ void combine_kernel(float* __restrict__ y) {
    int t    = (blockIdx.x * blockDim.x + threadIdx.x) >> 5;
    int lane = threadIdx.x & 31;
    if (t >= T_TOK) return;
    int   s0 = g_tok_slot[2 * t],  s1 = g_tok_slot[2 * t + 1];
    float w0 = g_tok_w[2 * t],     w1 = g_tok_w[2 * t + 1];
    const float4* o0 = reinterpret_cast<const float4*>(g_O + (size_t)s0 * DIM);
    const float4* o1 = reinterpret_cast<const float4*>(g_O + (size_t)s1 * DIM);
    float4* yr = reinterpret_cast<float4*>(y + (size_t)t * DIM);
#pragma unroll
    for (int i = 0; i < 8; i++) {
        int c = lane + 32 * i;
        float4 a = o0[c], b = o1[c], r;
        r.x = w0 * a.x + w1 * b.x;
        r.y = w0 * a.y + w1 * b.y;
        r.z = w0 * a.z + w1 * b.z;
        r.w = w0 * a.w + w1 * b.w;
        yr[c] = r;
    }
}

// ---------------- launcher ---------------------------------------------------
extern "C" void kernel_launch(void* const* d_in, const int* in_sizes, int n_in,
                              void* d_out, int out_size) {
    const float* x  = (const float*)d_in[0];
    const float* Wg = (const float*)d_in[1];
    const float* bg = (const float*)d_in[2];
    const float* W1 = (const float*)d_in[3];
    const float* b1 = (const float*)d_in[4];
    const float* W2 = (const float*)d_in[5];
    const float* b2 = (const float*)d_in[6];
    const float* W3 = (const float*)d_in[7];
    const float* b3 = (const float*)d_in[8];
    float* y = (float*)d_out;

    static cudaStream_t s1 = nullptr, s2 = nullptr;
    static cudaEvent_t  evF = nullptr, ev1 = nullptr, ev2 = nullptr;
    if (s1 == nullptr) {
        cudaStreamCreateWithFlags(&s1, cudaStreamNonBlocking);
        cudaStreamCreateWithFlags(&s2, cudaStreamNonBlocking);
        cudaEventCreateWithFlags(&evF, cudaEventDisableTiming);
        cudaEventCreateWithFlags(&ev1, cudaEventDisableTiming);
        cudaEventCreateWithFlags(&ev2, cudaEventDisableTiming);
        cudaFuncSetAttribute(gemm1_kernel, cudaFuncAttributeMaxDynamicSharedMemorySize, G1_SMEM);
        cudaFuncSetAttribute(gemm2_kernel, cudaFuncAttributeMaxDynamicSharedMemorySize, G2_SMEM);
    }

    // Fork: weight transposes on side streams, routing on the main stream.
    cudaEventRecord(evF, 0);
    cudaStreamWaitEvent(s1, evF, 0);
    cudaStreamWaitEvent(s2, evF, 0);

    convt_kernel<<<dim3(INTER / 32, DIM / 32, NEXP), dim3(32, 8), 0, s1>>>(W1, 0, DIM, INTER);
    convt_kernel<<<dim3(INTER / 32, DIM / 32, NEXP), dim3(32, 8), 0, s1>>>(W3, 1, DIM, INTER);
    cudaEventRecord(ev1, s1);

    convt_kernel<<<dim3(DIM / 32, INTER / 32, NEXP), dim3(32, 8), 0, s2>>>(W2, 2, INTER, DIM);
    cudaEventRecord(ev2, s2);

    gate_kernel<<<T_TOK / 32, 256>>>(x, Wg, bg);
    offsets_kernel<<<1, 256>>>();
    assign_gather_kernel<<<NA / 8, 256>>>(x);

    cudaStreamWaitEvent(0, ev1, 0);   // W1/W3 ready
    gemm1_kernel<<<dim3(INTER / BN, NT_MAX), 512, G1_SMEM>>>(b1, b3);
    cudaStreamWaitEvent(0, ev2, 0);   // W2 ready (normally long done)
    gemm2_kernel<<<dim3(DIM / BN, NT_MAX), 512, G2_SMEM>>>(b2);
    combine_kernel<<<T_TOK / 8, 256>>>(y);
}